// round 1
// baseline (speedup 1.0000x reference)
#include <cuda_runtime.h>
#include <cuda_bf16.h>

// Problem constants
#define BS_      8
#define SEQ_     1024
#define DM_      1024
#define NH_      16
#define DK_      64
#define NBH_     (BS_ * NH_)          // 128
#define TOK_     (BS_ * SEQ_)         // 8192
#define SCALE_   0.125f

// Scratch buffers (allocation-free rule -> __device__ globals)
__device__ float g_q  [NBH_ * SEQ_ * DK_];   // [bh, s, d]
__device__ float g_kT [NBH_ * DK_ * SEQ_];   // [bh, d, s]
__device__ float g_v  [NBH_ * SEQ_ * DK_];   // [bh, s, d]
__device__ float g_ctx[TOK_ * DM_];          // [token, h*64+d]

// ---------------------------------------------------------------------------
// Generic register-tiled SGEMM.
// A: [M,K] row-major (row stride K), B: [K,N] row-major (row stride N).
// MODE 0: C[row*N+col] = acc + bias[col]                    (plain, outproj)
// MODE 1: out[(b*16+h)*65536 + s*64 + d] = acc + bias[col]  (q/v layout)
// MODE 2: out[(b*16+h)*65536 + d*1024 + s] = acc + bias[col](kT layout)
// MODE 3: C[row*N+col] = acc * scale                        (scores, batched z)
// MODE 4: ctx[(b*1024+row)*1024 + h*64 + col] = acc         (ctx, bh = z)
// ---------------------------------------------------------------------------
template<int BM, int BN, int BK, int TM, int TN, int MODE>
__global__ __launch_bounds__((BM/TM)*(BN/TN))
void gemm_kernel(const float* __restrict__ A, const float* __restrict__ B,
                 const float* __restrict__ bias, float* __restrict__ C,
                 int M, int N, int K,
                 long long aBatch, long long bBatch, long long cBatch,
                 float scale)
{
    constexpr int TX = BN / TN;
    constexpr int TY = BM / TM;
    constexpr int T  = TX * TY;
    const int t  = threadIdx.x;
    const int tx = t % TX;
    const int ty = t / TX;
    const int bz = blockIdx.z;

    A += (long long)bz * aBatch;
    B += (long long)bz * bBatch;
    C += (long long)bz * cBatch;

    const int m0 = blockIdx.y * BM;
    const int n0 = blockIdx.x * BN;

    __shared__ float As[BK][BM];
    __shared__ float Bs[BK][BN];

    float acc[TM][TN];
    #pragma unroll
    for (int i = 0; i < TM; i++)
        #pragma unroll
        for (int j = 0; j < TN; j++) acc[i][j] = 0.0f;

    constexpr int LA = (BM * BK) / (4 * T);   // float4 loads of A per thread
    constexpr int LB = (BK * BN) / (4 * T);   // float4 loads of B per thread
    static_assert(LA >= 1 && LB >= 1, "tile/thread mismatch");

    for (int k0 = 0; k0 < K; k0 += BK) {
        #pragma unroll
        for (int i = 0; i < LA; i++) {
            int idx = t + i * T;                 // float4 index inside A tile
            int row = idx / (BK / 4);
            int kc  = (idx % (BK / 4)) * 4;
            float4 va = *(const float4*)(A + (long long)(m0 + row) * K + k0 + kc);
            As[kc + 0][row] = va.x;
            As[kc + 1][row] = va.y;
            As[kc + 2][row] = va.z;
            As[kc + 3][row] = va.w;
        }
        #pragma unroll
        for (int i = 0; i < LB; i++) {
            int idx = t + i * T;                 // float4 index inside B tile
            int row = idx / (BN / 4);
            int nc  = (idx % (BN / 4)) * 4;
            *(float4*)&Bs[row][nc] =
                *(const float4*)(B + (long long)(k0 + row) * N + n0 + nc);
        }
        __syncthreads();

        #pragma unroll
        for (int k = 0; k < BK; k++) {
            float a[TM], b[TN];
            #pragma unroll
            for (int i = 0; i < TM; i++) a[i] = As[k][ty * TM + i];
            #pragma unroll
            for (int j = 0; j < TN; j++) b[j] = Bs[k][tx * TN + j];
            #pragma unroll
            for (int i = 0; i < TM; i++)
                #pragma unroll
                for (int j = 0; j < TN; j++)
                    acc[i][j] = fmaf(a[i], b[j], acc[i][j]);
        }
        __syncthreads();
    }

    #pragma unroll
    for (int i = 0; i < TM; i++) {
        const int row = m0 + ty * TM + i;
        #pragma unroll
        for (int j = 0; j < TN; j++) {
            const int col = n0 + tx * TN + j;
            float v = acc[i][j];
            if (MODE == 0) {
                C[(long long)row * N + col] = v + bias[col];
            } else if (MODE == 1) {
                int b = row >> 10, s = row & 1023, h = col >> 6, d = col & 63;
                C[(((long long)(b * NH_ + h)) << 16) + s * DK_ + d] = v + bias[col];
            } else if (MODE == 2) {
                int b = row >> 10, s = row & 1023, h = col >> 6, d = col & 63;
                C[(((long long)(b * NH_ + h)) << 16) + d * SEQ_ + s] = v + bias[col];
            } else if (MODE == 3) {
                C[(long long)row * N + col] = v * scale;
            } else { // MODE 4
                int b = bz >> 4, h = bz & 15;
                C[((long long)(b * SEQ_ + row)) * DM_ + h * DK_ + col] = v;
            }
        }
    }
}

// ---------------------------------------------------------------------------
// Row softmax: one block per row of 1024, 256 threads * float4.
// ---------------------------------------------------------------------------
__global__ __launch_bounds__(256)
void softmax_kernel(const float* __restrict__ S, float* __restrict__ P)
{
    const long long row = blockIdx.x;
    const float4* s4 = (const float4*)(S + (row << 10));
    float4*       p4 = (float4*)(P + (row << 10));
    const int t = threadIdx.x;

    float4 v = s4[t];
    float m = fmaxf(fmaxf(v.x, v.y), fmaxf(v.z, v.w));
    #pragma unroll
    for (int o = 16; o; o >>= 1) m = fmaxf(m, __shfl_xor_sync(0xffffffffu, m, o));

    __shared__ float smax[8];
    __shared__ float ssum[8];
    if ((t & 31) == 0) smax[t >> 5] = m;
    __syncthreads();
    m = smax[0];
    #pragma unroll
    for (int w = 1; w < 8; w++) m = fmaxf(m, smax[w]);

    float4 e;
    e.x = expf(v.x - m); e.y = expf(v.y - m);
    e.z = expf(v.z - m); e.w = expf(v.w - m);
    float sum = e.x + e.y + e.z + e.w;
    #pragma unroll
    for (int o = 16; o; o >>= 1) sum += __shfl_xor_sync(0xffffffffu, sum, o);
    if ((t & 31) == 0) ssum[t >> 5] = sum;
    __syncthreads();
    sum = ssum[0] + ssum[1] + ssum[2] + ssum[3]
        + ssum[4] + ssum[5] + ssum[6] + ssum[7];

    const float inv = 1.0f / sum;
    e.x *= inv; e.y *= inv; e.z *= inv; e.w *= inv;
    p4[t] = e;
}

// ---------------------------------------------------------------------------
// Launch
// ---------------------------------------------------------------------------
extern "C" void kernel_launch(void* const* d_in, const int* in_sizes, int n_in,
                              void* d_out, int out_size)
{
    const float* Q    = (const float*)d_in[0];
    const float* K    = (const float*)d_in[1];
    const float* V    = (const float*)d_in[2];
    const float* WQ_w = (const float*)d_in[3];
    const float* WQ_b = (const float*)d_in[4];
    const float* WK_w = (const float*)d_in[5];
    const float* WK_b = (const float*)d_in[6];
    const float* WV_w = (const float*)d_in[7];
    const float* WV_b = (const float*)d_in[8];
    const float* Wo_w = (const float*)d_in[9];
    const float* Wo_b = (const float*)d_in[10];

    float* out    = (float*)d_out;                               // [8,1024,1024]
    float* attn_w = out    + (long long)TOK_ * DM_;              // [8,16,1024,1024]
    float* attn_s = attn_w + (long long)NBH_ * SEQ_ * SEQ_;      // [8,16,1024,1024]

    float *p_q, *p_kT, *p_v, *p_ctx;
    cudaGetSymbolAddress((void**)&p_q,   g_q);
    cudaGetSymbolAddress((void**)&p_kT,  g_kT);
    cudaGetSymbolAddress((void**)&p_v,   g_v);
    cudaGetSymbolAddress((void**)&p_ctx, g_ctx);

    // 1-3. QKV projections  (8192 x 1024 x 1024 each)
    gemm_kernel<128,128,8,8,8,1><<<dim3(8,64,1),256>>>(
        Q, WQ_w, WQ_b, p_q,  TOK_, DM_, DM_, 0,0,0, 1.0f);
    gemm_kernel<128,128,8,8,8,2><<<dim3(8,64,1),256>>>(
        K, WK_w, WK_b, p_kT, TOK_, DM_, DM_, 0,0,0, 1.0f);
    gemm_kernel<128,128,8,8,8,1><<<dim3(8,64,1),256>>>(
        V, WV_w, WV_b, p_v,  TOK_, DM_, DM_, 0,0,0, 1.0f);

    // 4. scores = q @ kT * SCALE, batched over bh (z=128)
    gemm_kernel<128,128,8,8,8,3><<<dim3(8,8,128),256>>>(
        p_q, p_kT, nullptr, attn_s, SEQ_, SEQ_, DK_,
        (long long)SEQ_*DK_, (long long)DK_*SEQ_, (long long)SEQ_*SEQ_, SCALE_);

    // 5. softmax over last dim (131072 rows)
    softmax_kernel<<<NBH_ * SEQ_, 256>>>(attn_s, attn_w);

    // 6. ctx = P @ v, batched over bh; output merged-head layout [token, h*64+d]
    gemm_kernel<128,64,16,8,4,4><<<dim3(1,8,128),256>>>(
        attn_w, p_v, nullptr, p_ctx, SEQ_, DK_, SEQ_,
        (long long)SEQ_*SEQ_, (long long)SEQ_*DK_, 0, 1.0f);

    // 7. output projection
    gemm_kernel<128,128,8,8,8,0><<<dim3(8,64,1),256>>>(
        p_ctx, Wo_w, Wo_b, out, TOK_, DM_, DM_, 0,0,0, 1.0f);
}

// round 4
// speedup vs baseline: 2.6065x; 2.6065x over previous
#include <cuda_runtime.h>
#include <cstdint>

#define BS_    8
#define SEQ_   1024
#define DM_    1024
#define NH_    16
#define DK_    64
#define NBH_   128
#define TOK_   8192
#define SCALE_ 0.125f

// Scratch (allocation-free rule -> __device__ globals)
__device__ float g_q  [NBH_ * SEQ_ * DK_];   // [bh, s, d]
__device__ float g_k  [NBH_ * SEQ_ * DK_];   // [bh, s, d]
__device__ float g_vT [NBH_ * DK_ * SEQ_];   // [bh, d, s]
__device__ float g_ctx[TOK_ * DM_];          // [token, h*64+d]
__device__ float g_wqT[DM_ * DM_];
__device__ float g_wkT[DM_ * DM_];
__device__ float g_wvT[DM_ * DM_];
__device__ float g_woT[DM_ * DM_];

// ---------------------------------------------------------------------------
// helpers
// ---------------------------------------------------------------------------
__device__ __forceinline__ uint32_t smem_u32(const void* p) {
    uint32_t a;
    asm("{ .reg .u64 t; cvta.to.shared.u64 t, %1; cvt.u32.u64 %0, t; }"
        : "=r"(a) : "l"(p));
    return a;
}
__device__ __forceinline__ void cp_async16(uint32_t s, const void* g) {
    asm volatile("cp.async.cg.shared.global [%0], [%1], 16;" :: "r"(s), "l"(g));
}
#define CP_COMMIT() asm volatile("cp.async.commit_group;" ::: "memory")
#define CP_WAIT(n)  asm volatile("cp.async.wait_group %0;" :: "n"(n) : "memory")

__device__ __forceinline__ uint32_t f2tf32(float f) {
    uint32_t r;
    asm("cvt.rna.tf32.f32 %0, %1;" : "=r"(r) : "f"(f));
    return r;
}
__device__ __forceinline__ void mma8(float* c, const uint32_t* a, const uint32_t* b) {
    asm volatile("mma.sync.aligned.m16n8k8.row.col.f32.tf32.tf32.f32 "
        "{%0,%1,%2,%3}, {%4,%5,%6,%7}, {%8,%9}, {%0,%1,%2,%3};"
        : "+f"(c[0]), "+f"(c[1]), "+f"(c[2]), "+f"(c[3])
        : "r"(a[0]), "r"(a[1]), "r"(a[2]), "r"(a[3]), "r"(b[0]), "r"(b[1]));
}

// ---------------------------------------------------------------------------
// tf32 mma.sync GEMM: C[M,N] = A[M,K] @ B[N,K]^T  (+ bias / scale / relayout)
// BM = 128 fixed. 8 warps: (128/WM) x (BN/WN) grid, warp tile WM x WN.
// MODE 0: plain + bias           MODE 1: [bh,s,64] + bias
// MODE 2: vT [bh,d,s] + bias     MODE 3: plain * scale (batched z)
// MODE 4: ctx [token, h*64+d]    (batched z = bh)
// ---------------------------------------------------------------------------
template<int BN, int WM, int WN, int MODE>
__global__ __launch_bounds__(256)
void gemm_mma(const float* __restrict__ A, const float* __restrict__ B,
              const float* __restrict__ bias, float* __restrict__ C,
              int M, int N, int K,
              long long aB, long long bB, long long cB, float scale)
{
    constexpr int PA   = 20;            // smem pitch (floats) for 16-col stage
    constexpr int NWN  = BN / WN;       // warps along n
    constexpr int NMT  = WM / 16;
    constexpr int NNT  = WN / 8;
    constexpr int ASTG = 128 * PA * 4;  // bytes per A stage
    constexpr int BSTG = BN * PA * 4;
    static_assert((128 / WM) * NWN == 8, "warp grid");

    extern __shared__ char smem[];
    const uint32_t sb = smem_u32(smem);
    const int t = threadIdx.x, lane = t & 31, wid = t >> 5;
    const int bz = blockIdx.z;
    const int m0 = blockIdx.y * 128, n0 = blockIdx.x * BN;

    A += (long long)bz * aB;
    B += (long long)bz * bB;
    C += (long long)bz * cB;

    const int wm0 = (wid / NWN) * WM;
    const int wn0 = (wid % NWN) * WN;
    constexpr uint32_t offB = 2 * ASTG;

    float acc[NMT][NNT][4];
    #pragma unroll
    for (int i = 0; i < NMT; i++)
        #pragma unroll
        for (int j = 0; j < NNT; j++)
            #pragma unroll
            for (int q = 0; q < 4; q++) acc[i][j][q] = 0.0f;

    const int NT = K / 16;

    auto issue = [&](int kt, int buf) {
        const int k0 = kt * 16;
        #pragma unroll
        for (int i = 0; i < 2; i++) {            // A: 512 float4 / 256 thr
            int idx = t + i * 256;
            int row = idx >> 2, c4 = idx & 3;
            cp_async16(sb + buf * ASTG + (uint32_t)(row * PA + c4 * 4) * 4,
                       A + (long long)(m0 + row) * K + k0 + c4 * 4);
        }
        #pragma unroll
        for (int i = 0; i < BN / 64; i++) {      // B: BN*4 float4 / 256 thr
            int idx = t + i * 256;
            int row = idx >> 2, c4 = idx & 3;
            cp_async16(sb + offB + buf * BSTG + (uint32_t)(row * PA + c4 * 4) * 4,
                       B + (long long)(n0 + row) * K + k0 + c4 * 4);
        }
    };

    issue(0, 0);
    CP_COMMIT();

    for (int kt = 0; kt < NT; kt++) {
        const int buf = kt & 1;
        if (kt + 1 < NT) { issue(kt + 1, buf ^ 1); CP_COMMIT(); CP_WAIT(1); }
        else             { CP_WAIT(0); }
        __syncthreads();

        const float* As_ = (const float*)(smem + buf * ASTG);
        const float* Bs_ = (const float*)(smem + offB + buf * BSTG);

        #pragma unroll
        for (int kg = 0; kg < 2; kg++) {
            const int k0 = kg * 8 + (lane & 3);
            uint32_t af[NMT][4], bf[NNT][2];
            #pragma unroll
            for (int mt = 0; mt < NMT; mt++) {
                int r = wm0 + mt * 16 + (lane >> 2);
                af[mt][0] = f2tf32(As_[r * PA + k0]);
                af[mt][1] = f2tf32(As_[(r + 8) * PA + k0]);
                af[mt][2] = f2tf32(As_[r * PA + k0 + 4]);
                af[mt][3] = f2tf32(As_[(r + 8) * PA + k0 + 4]);
            }
            #pragma unroll
            for (int nt = 0; nt < NNT; nt++) {
                int n = wn0 + nt * 8 + (lane >> 2);
                bf[nt][0] = f2tf32(Bs_[n * PA + k0]);
                bf[nt][1] = f2tf32(Bs_[n * PA + k0 + 4]);
            }
            #pragma unroll
            for (int mt = 0; mt < NMT; mt++)
                #pragma unroll
                for (int nt = 0; nt < NNT; nt++)
                    mma8(acc[mt][nt], af[mt], bf[nt]);
        }
        __syncthreads();
    }

    // ---- Epilogue: regs -> padded SMEM -> coalesced / relayout GMEM ----
    constexpr int EP = BN + 4;
    float* ep = (float*)smem;
    #pragma unroll
    for (int mt = 0; mt < NMT; mt++) {
        #pragma unroll
        for (int nt = 0; nt < NNT; nt++) {
            int r = wm0 + mt * 16 + (lane >> 2);
            int c = wn0 + nt * 8 + (lane & 3) * 2;
            *(float2*)&ep[r * EP + c]       = make_float2(acc[mt][nt][0], acc[mt][nt][1]);
            *(float2*)&ep[(r + 8) * EP + c] = make_float2(acc[mt][nt][2], acc[mt][nt][3]);
        }
    }
    __syncthreads();

    if (MODE == 2) {
        // transposed copy-out: vT[bh, d, s]
        #pragma unroll
        for (int i = 0; i < BN / 8; i++) {
            int col_l = (t >> 5) + 8 * i;
            int sl = (t & 31) * 4;
            float bv = bias[n0 + col_l];
            float4 v;
            v.x = ep[(sl + 0) * EP + col_l] + bv;
            v.y = ep[(sl + 1) * EP + col_l] + bv;
            v.z = ep[(sl + 2) * EP + col_l] + bv;
            v.w = ep[(sl + 3) * EP + col_l] + bv;
            int tok0 = m0 + sl;
            int b = tok0 >> 10, s = tok0 & 1023;
            int colg = n0 + col_l, h = colg >> 6, d = colg & 63;
            *(float4*)&C[(((long long)(b * NH_ + h)) << 16) + (long long)d * SEQ_ + s] = v;
        }
    } else {
        constexpr int NC4  = BN / 4;
        constexpr int ITER = 128 * NC4 / 256;
        #pragma unroll
        for (int i = 0; i < ITER; i++) {
            int idx = t + i * 256;
            int r_ = idx / NC4, c4 = idx % NC4;
            float4 v = *(float4*)&ep[r_ * EP + 4 * c4];
            int colg = n0 + 4 * c4;
            if (MODE == 0) {
                float4 bv = *(const float4*)&bias[colg];
                v.x += bv.x; v.y += bv.y; v.z += bv.z; v.w += bv.w;
                *(float4*)&C[(long long)(m0 + r_) * N + colg] = v;
            } else if (MODE == 1) {
                float4 bv = *(const float4*)&bias[colg];
                v.x += bv.x; v.y += bv.y; v.z += bv.z; v.w += bv.w;
                int tok = m0 + r_, b = tok >> 10, s = tok & 1023;
                int h = colg >> 6, d = colg & 63;
                *(float4*)&C[(((long long)(b * NH_ + h)) << 16) + s * DK_ + d] = v;
            } else if (MODE == 3) {
                v.x *= scale; v.y *= scale; v.z *= scale; v.w *= scale;
                *(float4*)&C[(long long)(m0 + r_) * N + colg] = v;
            } else { // MODE 4
                int b = bz >> 4, h = bz & 15;
                *(float4*)&C[((long long)(b * SEQ_ + m0 + r_)) * DM_ + h * DK_ + colg] = v;
            }
        }
    }
}

// ---------------------------------------------------------------------------
// 1024x1024 transpose (32x32 tiles)
// ---------------------------------------------------------------------------
__global__ __launch_bounds__(256)
void transpose_k(const float* __restrict__ W, float* __restrict__ WT)
{
    __shared__ float tile[32][33];
    int bx = blockIdx.x * 32, by = blockIdx.y * 32;
    int tx = threadIdx.x & 31, ty = threadIdx.x >> 5;
    #pragma unroll
    for (int j = ty; j < 32; j += 8)
        tile[j][tx] = W[(long long)(by + j) * DM_ + bx + tx];
    __syncthreads();
    #pragma unroll
    for (int j = ty; j < 32; j += 8)
        WT[(long long)(bx + j) * DM_ + by + tx] = tile[tx][j];
}

// ---------------------------------------------------------------------------
// Row softmax (1024 cols), 256 threads
// ---------------------------------------------------------------------------
__global__ __launch_bounds__(256)
void softmax_kernel(const float* __restrict__ S, float* __restrict__ P)
{
    const long long row = blockIdx.x;
    const float4* s4 = (const float4*)(S + (row << 10));
    float4*       p4 = (float4*)(P + (row << 10));
    const int t = threadIdx.x;

    float4 v = s4[t];
    float m = fmaxf(fmaxf(v.x, v.y), fmaxf(v.z, v.w));
    #pragma unroll
    for (int o = 16; o; o >>= 1) m = fmaxf(m, __shfl_xor_sync(0xffffffffu, m, o));

    __shared__ float smax[8], ssum[8];
    if ((t & 31) == 0) smax[t >> 5] = m;
    __syncthreads();
    m = smax[0];
    #pragma unroll
    for (int w = 1; w < 8; w++) m = fmaxf(m, smax[w]);

    float4 e;
    e.x = expf(v.x - m); e.y = expf(v.y - m);
    e.z = expf(v.z - m); e.w = expf(v.w - m);
    float sum = e.x + e.y + e.z + e.w;
    #pragma unroll
    for (int o = 16; o; o >>= 1) sum += __shfl_xor_sync(0xffffffffu, sum, o);
    if ((t & 31) == 0) ssum[t >> 5] = sum;
    __syncthreads();
    sum = ssum[0] + ssum[1] + ssum[2] + ssum[3]
        + ssum[4] + ssum[5] + ssum[6] + ssum[7];

    const float inv = 1.0f / sum;
    e.x *= inv; e.y *= inv; e.z *= inv; e.w *= inv;
    p4[t] = e;
}

// ---------------------------------------------------------------------------
// Launch
// ---------------------------------------------------------------------------
static constexpr int SMEM_BIG = 128 * (128 + 4) * 4;  // 67584 (epi dominates)
static constexpr int SMEM_CTX = 128 * (64 + 4) * 4;   // 34816

extern "C" void kernel_launch(void* const* d_in, const int* in_sizes, int n_in,
                              void* d_out, int out_size)
{
    const float* Q    = (const float*)d_in[0];
    const float* K    = (const float*)d_in[1];
    const float* V    = (const float*)d_in[2];
    const float* WQ_w = (const float*)d_in[3];
    const float* WQ_b = (const float*)d_in[4];
    const float* WK_w = (const float*)d_in[5];
    const float* WK_b = (const float*)d_in[6];
    const float* WV_w = (const float*)d_in[7];
    const float* WV_b = (const float*)d_in[8];
    const float* Wo_w = (const float*)d_in[9];
    const float* Wo_b = (const float*)d_in[10];

    float* out    = (float*)d_out;
    float* attn_w = out    + (long long)TOK_ * DM_;
    float* attn_s = attn_w + (long long)NBH_ * SEQ_ * SEQ_;

    float *p_q, *p_k, *p_vT, *p_ctx, *p_wqT, *p_wkT, *p_wvT, *p_woT;
    cudaGetSymbolAddress((void**)&p_q,   g_q);
    cudaGetSymbolAddress((void**)&p_k,   g_k);
    cudaGetSymbolAddress((void**)&p_vT,  g_vT);
    cudaGetSymbolAddress((void**)&p_ctx, g_ctx);
    cudaGetSymbolAddress((void**)&p_wqT, g_wqT);
    cudaGetSymbolAddress((void**)&p_wkT, g_wkT);
    cudaGetSymbolAddress((void**)&p_wvT, g_wvT);
    cudaGetSymbolAddress((void**)&p_woT, g_woT);

    cudaFuncSetAttribute(gemm_mma<128,64,32,0>, cudaFuncAttributeMaxDynamicSharedMemorySize, SMEM_BIG);
    cudaFuncSetAttribute(gemm_mma<128,64,32,1>, cudaFuncAttributeMaxDynamicSharedMemorySize, SMEM_BIG);
    cudaFuncSetAttribute(gemm_mma<128,64,32,2>, cudaFuncAttributeMaxDynamicSharedMemorySize, SMEM_BIG);
    cudaFuncSetAttribute(gemm_mma<128,64,32,3>, cudaFuncAttributeMaxDynamicSharedMemorySize, SMEM_BIG);
    cudaFuncSetAttribute(gemm_mma<64,32,32,4>,  cudaFuncAttributeMaxDynamicSharedMemorySize, SMEM_CTX);

    // 0. Transpose weights -> [N,K]
    dim3 tg(32, 32);
    transpose_k<<<tg, 256>>>(WQ_w, p_wqT);
    transpose_k<<<tg, 256>>>(WK_w, p_wkT);
    transpose_k<<<tg, 256>>>(WV_w, p_wvT);
    transpose_k<<<tg, 256>>>(Wo_w, p_woT);

    // 1-3. QKV projections (8192 x 1024 x 1024)
    gemm_mma<128,64,32,1><<<dim3(8,64,1), 256, SMEM_BIG>>>(
        Q, p_wqT, WQ_b, p_q,  TOK_, DM_, DM_, 0,0,0, 1.0f);
    gemm_mma<128,64,32,1><<<dim3(8,64,1), 256, SMEM_BIG>>>(
        K, p_wkT, WK_b, p_k,  TOK_, DM_, DM_, 0,0,0, 1.0f);
    gemm_mma<128,64,32,2><<<dim3(8,64,1), 256, SMEM_BIG>>>(
        V, p_wvT, WV_b, p_vT, TOK_, DM_, DM_, 0,0,0, 1.0f);

    // 4. scores = q @ k^T * SCALE (batched over bh)
    gemm_mma<128,64,32,3><<<dim3(8,8,128), 256, SMEM_BIG>>>(
        p_q, p_k, nullptr, attn_s, SEQ_, SEQ_, DK_,
        (long long)SEQ_*DK_, (long long)SEQ_*DK_, (long long)SEQ_*SEQ_, SCALE_);

    // 5. softmax
    softmax_kernel<<<NBH_ * SEQ_, 256>>>(attn_s, attn_w);

    // 6. ctx = P @ v (batched over bh), merged-head layout
    gemm_mma<64,32,32,4><<<dim3(1,8,128), 256, SMEM_CTX>>>(
        attn_w, p_vT, nullptr, p_ctx, SEQ_, DK_, SEQ_,
        (long long)SEQ_*SEQ_, (long long)DK_*SEQ_, 0, 1.0f);

    // 7. output projection
    gemm_mma<128,64,32,0><<<dim3(8,64,1), 256, SMEM_BIG>>>(
        p_ctx, p_woT, Wo_b, out, TOK_, DM_, DM_, 0,0,0, 1.0f);
}

// round 6
// speedup vs baseline: 4.0267x; 1.5449x over previous
#include <cuda_runtime.h>
#include <cuda_fp16.h>
#include <cstdint>

#define BS_    8
#define SEQ_   1024
#define DM_    1024
#define NH_    16
#define DK_    64
#define NBH_   128
#define TOK_   8192
#define SCALE_ 0.125f

// Scratch (allocation-free rule -> __device__ globals)
__device__ __half g_Q16[TOK_ * DM_];
__device__ __half g_K16[TOK_ * DM_];
__device__ __half g_V16[TOK_ * DM_];
__device__ __half g_q  [NBH_ * SEQ_ * DK_];   // [bh, s, d] fp16
__device__ __half g_k  [NBH_ * SEQ_ * DK_];   // [bh, s, d] fp16
__device__ float  g_vT [NBH_ * DK_ * SEQ_];   // [bh, d, s] fp32 (tf32 ctx B)
__device__ __half g_ctx[TOK_ * DM_];          // [token, h*64+d] fp16
__device__ __half g_wqT[DM_ * DM_];
__device__ __half g_wkT[DM_ * DM_];
__device__ __half g_wvT[DM_ * DM_];
__device__ __half g_woT[DM_ * DM_];

// ---------------------------------------------------------------------------
// helpers
// ---------------------------------------------------------------------------
__device__ __forceinline__ uint32_t smem_u32(const void* p) {
    uint32_t a;
    asm("{ .reg .u64 t; cvta.to.shared.u64 t, %1; cvt.u32.u64 %0, t; }"
        : "=r"(a) : "l"(p));
    return a;
}
__device__ __forceinline__ void cp_async16(uint32_t s, const void* g) {
    asm volatile("cp.async.cg.shared.global [%0], [%1], 16;" :: "r"(s), "l"(g));
}
#define CP_COMMIT() asm volatile("cp.async.commit_group;" ::: "memory")
#define CP_WAIT(n)  asm volatile("cp.async.wait_group %0;" :: "n"(n) : "memory")

__device__ __forceinline__ void ldmx4(uint32_t* r, uint32_t a) {
    asm volatile("ldmatrix.sync.aligned.m8n8.x4.shared.b16 {%0,%1,%2,%3}, [%4];"
        : "=r"(r[0]), "=r"(r[1]), "=r"(r[2]), "=r"(r[3]) : "r"(a));
}
__device__ __forceinline__ void ldmx2(uint32_t* r, uint32_t a) {
    asm volatile("ldmatrix.sync.aligned.m8n8.x2.shared.b16 {%0,%1}, [%2];"
        : "=r"(r[0]), "=r"(r[1]) : "r"(a));
}
__device__ __forceinline__ void mma16(float* c, const uint32_t* a, const uint32_t* b) {
    asm volatile("mma.sync.aligned.m16n8k16.row.col.f32.f16.f16.f32 "
        "{%0,%1,%2,%3}, {%4,%5,%6,%7}, {%8,%9}, {%0,%1,%2,%3};"
        : "+f"(c[0]), "+f"(c[1]), "+f"(c[2]), "+f"(c[3])
        : "r"(a[0]), "r"(a[1]), "r"(a[2]), "r"(a[3]), "r"(b[0]), "r"(b[1]));
}
__device__ __forceinline__ uint32_t f2tf32(float f) {
    uint32_t r;
    asm("cvt.rna.tf32.f32 %0, %1;" : "=r"(r) : "f"(f));
    return r;
}
__device__ __forceinline__ void mma8(float* c, const uint32_t* a, const uint32_t* b) {
    asm volatile("mma.sync.aligned.m16n8k8.row.col.f32.tf32.tf32.f32 "
        "{%0,%1,%2,%3}, {%4,%5,%6,%7}, {%8,%9}, {%0,%1,%2,%3};"
        : "+f"(c[0]), "+f"(c[1]), "+f"(c[2]), "+f"(c[3])
        : "r"(a[0]), "r"(a[1]), "r"(a[2]), "r"(a[3]), "r"(b[0]), "r"(b[1]));
}
__device__ __forceinline__ uint2 f4_to_h4(float4 v) {
    __half2 a = __floats2half2_rn(v.x, v.y);
    __half2 b = __floats2half2_rn(v.z, v.w);
    return make_uint2(*(uint32_t*)&a, *(uint32_t*)&b);
}

// ---------------------------------------------------------------------------
// fp16 mma GEMM: C[M,N] = A[M,K] @ B[N,K]^T  (A,B fp16 K-major, BK=32)
// MODE 0: fp32 + bias            MODE 1: half [bh,s,64] + bias
// MODE 2: fp32 vT [bh,d,s]+bias
// ---------------------------------------------------------------------------
template<typename TOUT, int BN, int WM, int WN, int MODE>
__global__ __launch_bounds__(256)
void gemm_h(const __half* __restrict__ A, const __half* __restrict__ B,
            const float* __restrict__ bias, TOUT* __restrict__ C,
            int M, int N, int K)
{
    constexpr int PH   = 40;                 // halves pitch for 32-half row
    constexpr int NWN  = BN / WN;
    constexpr int NMT  = WM / 16, NNT = WN / 8;
    constexpr int ASTG = 128 * PH * 2;       // bytes
    constexpr int BSTG = BN * PH * 2;
    static_assert((128 / WM) * NWN == 8, "warp grid");

    extern __shared__ char smem[];
    const uint32_t sb = smem_u32(smem);
    const int t = threadIdx.x, lane = t & 31, wid = t >> 5;
    const int m0 = blockIdx.y * 128, n0 = blockIdx.x * BN;

    const int wm0 = (wid / NWN) * WM;
    const int wn0 = (wid % NWN) * WN;
    constexpr uint32_t offB = 2 * ASTG;

    float acc[NMT][NNT][4];
    #pragma unroll
    for (int i = 0; i < NMT; i++)
        #pragma unroll
        for (int j = 0; j < NNT; j++)
            #pragma unroll
            for (int q = 0; q < 4; q++) acc[i][j][q] = 0.0f;

    const int NT = K / 32;

    auto issue = [&](int kt, int buf) {
        const int k0 = kt * 32;
        #pragma unroll
        for (int i = 0; i < 2; i++) {            // A: 512 cp16 / 256 thr
            int idx = t + i * 256;
            int row = idx >> 2, seg = idx & 3;
            cp_async16(sb + buf * ASTG + (uint32_t)(row * PH + seg * 8) * 2,
                       A + (long long)(m0 + row) * K + k0 + seg * 8);
        }
        #pragma unroll
        for (int i = 0; i < BN / 64; i++) {      // B: BN*4 cp16 / 256 thr
            int idx = t + i * 256;
            int row = idx >> 2, seg = idx & 3;
            cp_async16(sb + offB + buf * BSTG + (uint32_t)(row * PH + seg * 8) * 2,
                       B + (long long)(n0 + row) * K + k0 + seg * 8);
        }
    };

    issue(0, 0);
    CP_COMMIT();

    for (int kt = 0; kt < NT; kt++) {
        const int buf = kt & 1;
        if (kt + 1 < NT) { issue(kt + 1, buf ^ 1); CP_COMMIT(); CP_WAIT(1); }
        else             { CP_WAIT(0); }
        __syncthreads();

        const uint32_t ab = sb + buf * ASTG;
        const uint32_t bb = sb + offB + buf * BSTG;

        #pragma unroll
        for (int ks = 0; ks < 2; ks++) {
            uint32_t af[NMT][4], bf[NNT][2];
            #pragma unroll
            for (int mt = 0; mt < NMT; mt++)
                ldmx4(af[mt], ab + (uint32_t)((wm0 + mt * 16 + (lane & 15)) * PH
                                              + ks * 16 + (lane >> 4) * 8) * 2);
            #pragma unroll
            for (int nt = 0; nt < NNT; nt++)
                ldmx2(bf[nt], bb + (uint32_t)((wn0 + nt * 8 + (lane & 7)) * PH
                                              + ks * 16 + ((lane >> 3) & 1) * 8) * 2);
            #pragma unroll
            for (int mt = 0; mt < NMT; mt++)
                #pragma unroll
                for (int nt = 0; nt < NNT; nt++)
                    mma16(acc[mt][nt], af[mt], bf[nt]);
        }
        __syncthreads();
    }

    // ---- Epilogue: regs -> padded SMEM (fp32) -> relayout stores ----
    constexpr int EP = BN + 4;
    float* ep = (float*)smem;
    #pragma unroll
    for (int mt = 0; mt < NMT; mt++) {
        #pragma unroll
        for (int nt = 0; nt < NNT; nt++) {
            int r = wm0 + mt * 16 + (lane >> 2);
            int c = wn0 + nt * 8 + (lane & 3) * 2;
            *(float2*)&ep[r * EP + c]       = make_float2(acc[mt][nt][0], acc[mt][nt][1]);
            *(float2*)&ep[(r + 8) * EP + c] = make_float2(acc[mt][nt][2], acc[mt][nt][3]);
        }
    }
    __syncthreads();

    if (MODE == 2) {
        // transposed copy-out: vT[bh, d, s] (fp32)
        #pragma unroll
        for (int i = 0; i < BN / 8; i++) {
            int col_l = (t >> 5) + 8 * i;
            int sl = (t & 31) * 4;
            float bv = bias[n0 + col_l];
            float4 v;
            v.x = ep[(sl + 0) * EP + col_l] + bv;
            v.y = ep[(sl + 1) * EP + col_l] + bv;
            v.z = ep[(sl + 2) * EP + col_l] + bv;
            v.w = ep[(sl + 3) * EP + col_l] + bv;
            int tok0 = m0 + sl;
            int b = tok0 >> 10, s = tok0 & 1023;
            int colg = n0 + col_l, h = colg >> 6, d = colg & 63;
            *(float4*)&((float*)C)[(((long long)(b * NH_ + h)) << 16)
                                   + (long long)d * SEQ_ + s] = v;
        }
    } else {
        constexpr int NC4  = BN / 4;
        constexpr int ITER = 128 * NC4 / 256;
        #pragma unroll
        for (int i = 0; i < ITER; i++) {
            int idx = t + i * 256;
            int r_ = idx / NC4, c4 = idx % NC4;
            float4 v = *(float4*)&ep[r_ * EP + 4 * c4];
            int colg = n0 + 4 * c4;
            if (MODE == 0) {
                float4 bv = *(const float4*)&bias[colg];
                v.x += bv.x; v.y += bv.y; v.z += bv.z; v.w += bv.w;
                *(float4*)&((float*)C)[(long long)(m0 + r_) * N + colg] = v;
            } else { // MODE 1
                float4 bv = *(const float4*)&bias[colg];
                v.x += bv.x; v.y += bv.y; v.z += bv.z; v.w += bv.w;
                int tok = m0 + r_, b = tok >> 10, s = tok & 1023;
                int h = colg >> 6, d = colg & 63;
                *(uint2*)&((__half*)C)[(((long long)(b * NH_ + h)) << 16)
                                       + s * DK_ + d] = f4_to_h4(v);
            }
        }
    }
}

// ---------------------------------------------------------------------------
// tf32 mma.sync GEMM (R4-proven engine), used for ctx = attn_w(f32) @ vT(f32).
// Writes half ctx [token, h*64+d], batched z = bh.
// ---------------------------------------------------------------------------
template<int BN, int WM, int WN>
__global__ __launch_bounds__(256)
void gemm_ctx(const float* __restrict__ A, const float* __restrict__ B,
              __half* __restrict__ C, int M, int N, int K,
              long long aB, long long bB)
{
    constexpr int PA   = 20;
    constexpr int NWN  = BN / WN;
    constexpr int NMT  = WM / 16, NNT = WN / 8;
    constexpr int ASTG = 128 * PA * 4;
    constexpr int BSTG = BN * PA * 4;
    static_assert((128 / WM) * NWN == 8, "warp grid");

    extern __shared__ char smem[];
    const uint32_t sb = smem_u32(smem);
    const int t = threadIdx.x, lane = t & 31, wid = t >> 5;
    const int bz = blockIdx.z;
    const int m0 = blockIdx.y * 128, n0 = blockIdx.x * BN;

    A += (long long)bz * aB;
    B += (long long)bz * bB;

    const int wm0 = (wid / NWN) * WM;
    const int wn0 = (wid % NWN) * WN;
    constexpr uint32_t offB = 2 * ASTG;

    float acc[NMT][NNT][4];
    #pragma unroll
    for (int i = 0; i < NMT; i++)
        #pragma unroll
        for (int j = 0; j < NNT; j++)
            #pragma unroll
            for (int q = 0; q < 4; q++) acc[i][j][q] = 0.0f;

    const int NT = K / 16;

    auto issue = [&](int kt, int buf) {
        const int k0 = kt * 16;
        #pragma unroll
        for (int i = 0; i < 2; i++) {
            int idx = t + i * 256;
            int row = idx >> 2, c4 = idx & 3;
            cp_async16(sb + buf * ASTG + (uint32_t)(row * PA + c4 * 4) * 4,
                       A + (long long)(m0 + row) * K + k0 + c4 * 4);
        }
        #pragma unroll
        for (int i = 0; i < BN / 64; i++) {
            int idx = t + i * 256;
            int row = idx >> 2, c4 = idx & 3;
            cp_async16(sb + offB + buf * BSTG + (uint32_t)(row * PA + c4 * 4) * 4,
                       B + (long long)(n0 + row) * K + k0 + c4 * 4);
        }
    };

    issue(0, 0);
    CP_COMMIT();

    for (int kt = 0; kt < NT; kt++) {
        const int buf = kt & 1;
        if (kt + 1 < NT) { issue(kt + 1, buf ^ 1); CP_COMMIT(); CP_WAIT(1); }
        else             { CP_WAIT(0); }
        __syncthreads();

        const float* As_ = (const float*)(smem + buf * ASTG);
        const float* Bs_ = (const float*)(smem + offB + buf * BSTG);

        #pragma unroll
        for (int kg = 0; kg < 2; kg++) {
            const int k0 = kg * 8 + (lane & 3);
            uint32_t af[NMT][4], bf[NNT][2];
            #pragma unroll
            for (int mt = 0; mt < NMT; mt++) {
                int r = wm0 + mt * 16 + (lane >> 2);
                af[mt][0] = f2tf32(As_[r * PA + k0]);
                af[mt][1] = f2tf32(As_[(r + 8) * PA + k0]);
                af[mt][2] = f2tf32(As_[r * PA + k0 + 4]);
                af[mt][3] = f2tf32(As_[(r + 8) * PA + k0 + 4]);
            }
            #pragma unroll
            for (int nt = 0; nt < NNT; nt++) {
                int n = wn0 + nt * 8 + (lane >> 2);
                bf[nt][0] = f2tf32(Bs_[n * PA + k0]);
                bf[nt][1] = f2tf32(Bs_[n * PA + k0 + 4]);
            }
            #pragma unroll
            for (int mt = 0; mt < NMT; mt++)
                #pragma unroll
                for (int nt = 0; nt < NNT; nt++)
                    mma8(acc[mt][nt], af[mt], bf[nt]);
        }
        __syncthreads();
    }

    constexpr int EP = BN + 4;
    float* ep = (float*)smem;
    #pragma unroll
    for (int mt = 0; mt < NMT; mt++) {
        #pragma unroll
        for (int nt = 0; nt < NNT; nt++) {
            int r = wm0 + mt * 16 + (lane >> 2);
            int c = wn0 + nt * 8 + (lane & 3) * 2;
            *(float2*)&ep[r * EP + c]       = make_float2(acc[mt][nt][0], acc[mt][nt][1]);
            *(float2*)&ep[(r + 8) * EP + c] = make_float2(acc[mt][nt][2], acc[mt][nt][3]);
        }
    }
    __syncthreads();

    constexpr int NC4  = BN / 4;
    constexpr int ITER = 128 * NC4 / 256;
    #pragma unroll
    for (int i = 0; i < ITER; i++) {
        int idx = t + i * 256;
        int r_ = idx / NC4, c4 = idx % NC4;
        float4 v = *(float4*)&ep[r_ * EP + 4 * c4];
        int b = bz >> 4, h = bz & 15;
        *(uint2*)&C[((long long)(b * SEQ_ + m0 + r_)) * DM_
                    + h * DK_ + 4 * c4] = f4_to_h4(v);
    }
}

// ---------------------------------------------------------------------------
// Fused scores + softmax: one block = 32 q-rows x 1024 k-cols for one bh.
// Writes attn_s (fp32) and attn_w (fp32).
// ---------------------------------------------------------------------------
__global__ __launch_bounds__(256)
void fused_scores(const __half* __restrict__ q, const __half* __restrict__ k,
                  float* __restrict__ attn_s, float* __restrict__ attn_w)
{
    constexpr int PS = 1032;               // S pitch (floats)
    constexpr int PQ = 72;                 // half pitch
    constexpr uint32_t S_BYTES = 32 * PS * 4;        // 132096
    constexpr uint32_t Q_BYTES = 32 * PQ * 2;        // 4608
    constexpr uint32_t KSTG    = 128 * PQ * 2;       // 18432

    extern __shared__ char smem[];
    float* S = (float*)smem;
    const uint32_t sb  = smem_u32(smem);
    const uint32_t qs  = sb + S_BYTES;
    const uint32_t ks0 = qs + Q_BYTES;

    const int t = threadIdx.x, lane = t & 31, w = t >> 5;
    const int bh = blockIdx.y, m0 = blockIdx.x * 32;
    const __half* qg = q + (((long long)bh) << 16) + m0 * 64;
    const __half* kg = k + (((long long)bh) << 16);
    const long long orow = (((long long)bh) << 20) + (long long)m0 * 1024;

    // q tile: 32 rows x 64 halves (one cp16 per thread)
    { int row = t >> 3, seg = t & 7;
      cp_async16(qs + (uint32_t)(row * PQ + seg * 8) * 2, qg + row * 64 + seg * 8); }
    CP_COMMIT();

    auto issueK = [&](int c, int buf) {
        #pragma unroll
        for (int i = 0; i < 4; i++) {
            int idx = t + i * 256;
            int row = idx >> 3, seg = idx & 7;
            cp_async16(ks0 + buf * KSTG + (uint32_t)(row * PQ + seg * 8) * 2,
                       kg + (long long)(c * 128 + row) * 64 + seg * 8);
        }
    };
    issueK(0, 0);
    CP_COMMIT();
    CP_WAIT(1);              // q group done
    __syncthreads();

    // hoist q fragments (K=64 -> 4 k16 steps)
    uint32_t aq[2][4][4];
    #pragma unroll
    for (int mt = 0; mt < 2; mt++)
        #pragma unroll
        for (int ks = 0; ks < 4; ks++)
            ldmx4(aq[mt][ks], qs + (uint32_t)((mt * 16 + (lane & 15)) * PQ
                                              + ks * 16 + (lane >> 4) * 8) * 2);

    for (int c = 0; c < 8; c++) {
        const int buf = c & 1;
        if (c + 1 < 8) { issueK(c + 1, buf ^ 1); CP_COMMIT(); CP_WAIT(1); }
        else           { CP_WAIT(0); }
        __syncthreads();

        float acc[2][2][4] = {};
        const uint32_t kb = ks0 + buf * KSTG;
        #pragma unroll
        for (int ks = 0; ks < 4; ks++) {
            uint32_t bf[2][2];
            #pragma unroll
            for (int nt = 0; nt < 2; nt++)
                ldmx2(bf[nt], kb + (uint32_t)((w * 16 + nt * 8 + (lane & 7)) * PQ
                                              + ks * 16 + ((lane >> 3) & 1) * 8) * 2);
            #pragma unroll
            for (int mt = 0; mt < 2; mt++)
                #pragma unroll
                for (int nt = 0; nt < 2; nt++)
                    mma16(acc[mt][nt], aq[mt][ks], bf[nt]);
        }
        #pragma unroll
        for (int mt = 0; mt < 2; mt++)
            #pragma unroll
            for (int nt = 0; nt < 2; nt++) {
                int r   = mt * 16 + (lane >> 2);
                int col = c * 128 + w * 16 + nt * 8 + (lane & 3) * 2;
                *(float2*)&S[r * PS + col] =
                    make_float2(acc[mt][nt][0] * SCALE_, acc[mt][nt][1] * SCALE_);
                *(float2*)&S[(r + 8) * PS + col] =
                    make_float2(acc[mt][nt][2] * SCALE_, acc[mt][nt][3] * SCALE_);
            }
        __syncthreads();
    }

    // stream attn_s (raw scaled scores)
    #pragma unroll
    for (int i = 0; i < 32; i++) {
        int idx = t + i * 256;
        int r = idx >> 8, c4 = idx & 255;
        *(float4*)&attn_s[orow + r * 1024 + c4 * 4] = *(float4*)&S[r * PS + c4 * 4];
    }

    // softmax: warp w owns rows w*4 .. w*4+3
    for (int rr = 0; rr < 4; rr++) {
        const int r = w * 4 + rr;
        float4 vv[8];
        float m = -1e30f;
        #pragma unroll
        for (int i = 0; i < 8; i++) {
            vv[i] = *(float4*)&S[r * PS + lane * 4 + i * 128];
            m = fmaxf(m, fmaxf(fmaxf(vv[i].x, vv[i].y), fmaxf(vv[i].z, vv[i].w)));
        }
        #pragma unroll
        for (int o = 16; o; o >>= 1) m = fmaxf(m, __shfl_xor_sync(0xffffffffu, m, o));
        float sum = 0.0f;
        #pragma unroll
        for (int i = 0; i < 8; i++) {
            vv[i].x = __expf(vv[i].x - m); vv[i].y = __expf(vv[i].y - m);
            vv[i].z = __expf(vv[i].z - m); vv[i].w = __expf(vv[i].w - m);
            sum += vv[i].x + vv[i].y + vv[i].z + vv[i].w;
        }
        #pragma unroll
        for (int o = 16; o; o >>= 1) sum += __shfl_xor_sync(0xffffffffu, sum, o);
        const float inv = 1.0f / sum;
        const long long rb = orow + (long long)r * 1024;
        #pragma unroll
        for (int i = 0; i < 8; i++) {
            float4 wv = make_float4(vv[i].x * inv, vv[i].y * inv,
                                    vv[i].z * inv, vv[i].w * inv);
            *(float4*)&attn_w[rb + lane * 4 + i * 128] = wv;
        }
    }
}

// ---------------------------------------------------------------------------
// fp32 -> fp16 elementwise (vectorized x4)
// ---------------------------------------------------------------------------
__global__ __launch_bounds__(256)
void f2h(const float* __restrict__ x, __half* __restrict__ y, int n4)
{
    int i = blockIdx.x * 256 + threadIdx.x;
    if (i < n4) ((uint2*)y)[i] = f4_to_h4(((const float4*)x)[i]);
}

// ---------------------------------------------------------------------------
// 1024x1024 transpose + convert to half
// ---------------------------------------------------------------------------
__global__ __launch_bounds__(256)
void transpose_h(const float* __restrict__ W, __half* __restrict__ WT)
{
    __shared__ float tile[32][33];
    int bx = blockIdx.x * 32, by = blockIdx.y * 32;
    int tx = threadIdx.x & 31, ty = threadIdx.x >> 5;
    #pragma unroll
    for (int j = ty; j < 32; j += 8)
        tile[j][tx] = W[(long long)(by + j) * DM_ + bx + tx];
    __syncthreads();
    #pragma unroll
    for (int j = ty; j < 32; j += 8)
        WT[(long long)(bx + j) * DM_ + by + tx] = __float2half(tile[tx][j]);
}

// ---------------------------------------------------------------------------
// Launch
// ---------------------------------------------------------------------------
static constexpr int SMEM_BIG   = 128 * (128 + 4) * 4;                 // 67584
static constexpr int SMEM_CTX   = 128 * (64 + 4) * 4;                  // 34816
static constexpr int SMEM_FUSED = 32 * 1032 * 4 + 32 * 72 * 2 + 2 * 128 * 72 * 2; // 173568

extern "C" void kernel_launch(void* const* d_in, const int* in_sizes, int n_in,
                              void* d_out, int out_size)
{
    const float* Q    = (const float*)d_in[0];
    const float* K    = (const float*)d_in[1];
    const float* V    = (const float*)d_in[2];
    const float* WQ_w = (const float*)d_in[3];
    const float* WQ_b = (const float*)d_in[4];
    const float* WK_w = (const float*)d_in[5];
    const float* WK_b = (const float*)d_in[6];
    const float* WV_w = (const float*)d_in[7];
    const float* WV_b = (const float*)d_in[8];
    const float* Wo_w = (const float*)d_in[9];
    const float* Wo_b = (const float*)d_in[10];

    float* out    = (float*)d_out;
    float* attn_w = out    + (long long)TOK_ * DM_;
    float* attn_s = attn_w + (long long)NBH_ * SEQ_ * SEQ_;

    __half *p_Q16, *p_K16, *p_V16, *p_q, *p_k, *p_ctx;
    __half *p_wqT, *p_wkT, *p_wvT, *p_woT;
    float  *p_vT;
    cudaGetSymbolAddress((void**)&p_Q16, g_Q16);
    cudaGetSymbolAddress((void**)&p_K16, g_K16);
    cudaGetSymbolAddress((void**)&p_V16, g_V16);
    cudaGetSymbolAddress((void**)&p_q,   g_q);
    cudaGetSymbolAddress((void**)&p_k,   g_k);
    cudaGetSymbolAddress((void**)&p_vT,  g_vT);
    cudaGetSymbolAddress((void**)&p_ctx, g_ctx);
    cudaGetSymbolAddress((void**)&p_wqT, g_wqT);
    cudaGetSymbolAddress((void**)&p_wkT, g_wkT);
    cudaGetSymbolAddress((void**)&p_wvT, g_wvT);
    cudaGetSymbolAddress((void**)&p_woT, g_woT);

    cudaFuncSetAttribute(gemm_h<__half,128,64,32,1>, cudaFuncAttributeMaxDynamicSharedMemorySize, SMEM_BIG);
    cudaFuncSetAttribute(gemm_h<float ,128,64,32,2>, cudaFuncAttributeMaxDynamicSharedMemorySize, SMEM_BIG);
    cudaFuncSetAttribute(gemm_h<float ,128,64,32,0>, cudaFuncAttributeMaxDynamicSharedMemorySize, SMEM_BIG);
    cudaFuncSetAttribute(gemm_ctx<64,32,32>,         cudaFuncAttributeMaxDynamicSharedMemorySize, SMEM_CTX);
    cudaFuncSetAttribute(fused_scores, cudaFuncAttributeMaxDynamicSharedMemorySize, SMEM_FUSED);

    // 0. convert inputs + transpose weights to fp16
    const int n4 = TOK_ * DM_ / 4;
    f2h<<<n4 / 256, 256>>>(Q, p_Q16, n4);
    f2h<<<n4 / 256, 256>>>(K, p_K16, n4);
    f2h<<<n4 / 256, 256>>>(V, p_V16, n4);
    dim3 tg(32, 32);
    transpose_h<<<tg, 256>>>(WQ_w, p_wqT);
    transpose_h<<<tg, 256>>>(WK_w, p_wkT);
    transpose_h<<<tg, 256>>>(WV_w, p_wvT);
    transpose_h<<<tg, 256>>>(Wo_w, p_woT);

    // 1-3. QKV projections (8192 x 1024 x 1024, fp16)
    gemm_h<__half,128,64,32,1><<<dim3(8,64,1), 256, SMEM_BIG>>>(
        p_Q16, p_wqT, WQ_b, p_q,  TOK_, DM_, DM_);
    gemm_h<__half,128,64,32,1><<<dim3(8,64,1), 256, SMEM_BIG>>>(
        p_K16, p_wkT, WK_b, p_k,  TOK_, DM_, DM_);
    gemm_h<float ,128,64,32,2><<<dim3(8,64,1), 256, SMEM_BIG>>>(
        p_V16, p_wvT, WV_b, p_vT, TOK_, DM_, DM_);

    // 4+5. fused scores + softmax (writes attn_s, attn_w)
    fused_scores<<<dim3(32,128), 256, SMEM_FUSED>>>(p_q, p_k, attn_s, attn_w);

    // 6. ctx = attn_w @ vT (tf32, batched over bh), merged-head fp16 layout
    gemm_ctx<64,32,32><<<dim3(1,8,128), 256, SMEM_CTX>>>(
        attn_w, p_vT, p_ctx, SEQ_, DK_, SEQ_,
        (long long)SEQ_*SEQ_, (long long)DK_*SEQ_);

    // 7. output projection (fp32 out + bias)
    gemm_h<float,128,64,32,0><<<dim3(8,64,1), 256, SMEM_BIG>>>(
        p_ctx, p_woT, Wo_b, out, TOK_, DM_, DM_);
}

// round 8
// speedup vs baseline: 4.0898x; 1.0157x over previous
#include <cuda_runtime.h>
#include <cuda_fp16.h>
#include <cstdint>

#define BS_    8
#define SEQ_   1024
#define DM_    1024
#define NH_    16
#define DK_    64
#define NBH_   128
#define TOK_   8192
#define SCALE_ 0.125f

// Scratch (allocation-free rule -> __device__ globals)
__device__ __half g_Q16[TOK_ * DM_];
__device__ __half g_K16[TOK_ * DM_];
__device__ __half g_V16[TOK_ * DM_];
__device__ __half g_q  [NBH_ * SEQ_ * DK_];   // [bh, s, d] fp16
__device__ __half g_k  [NBH_ * SEQ_ * DK_];   // [bh, s, d] fp16
__device__ __half g_vT [NBH_ * DK_ * SEQ_];   // [bh, d, s] fp16
__device__ __half g_ctx[TOK_ * DM_];          // [token, h*64+d] fp16
__device__ __half g_wqT[DM_ * DM_];
__device__ __half g_wkT[DM_ * DM_];
__device__ __half g_wvT[DM_ * DM_];
__device__ __half g_woT[DM_ * DM_];

// ---------------------------------------------------------------------------
// helpers
// ---------------------------------------------------------------------------
__device__ __forceinline__ uint32_t smem_u32(const void* p) {
    uint32_t a;
    asm("{ .reg .u64 t; cvta.to.shared.u64 t, %1; cvt.u32.u64 %0, t; }"
        : "=r"(a) : "l"(p));
    return a;
}
__device__ __forceinline__ void cp_async16(uint32_t s, const void* g) {
    asm volatile("cp.async.cg.shared.global [%0], [%1], 16;" :: "r"(s), "l"(g));
}
#define CP_COMMIT() asm volatile("cp.async.commit_group;" ::: "memory")
#define CP_WAIT(n)  asm volatile("cp.async.wait_group %0;" :: "n"(n) : "memory")

__device__ __forceinline__ void ldmx4(uint32_t* r, uint32_t a) {
    asm volatile("ldmatrix.sync.aligned.m8n8.x4.shared.b16 {%0,%1,%2,%3}, [%4];"
        : "=r"(r[0]), "=r"(r[1]), "=r"(r[2]), "=r"(r[3]) : "r"(a));
}
__device__ __forceinline__ void ldmx2(uint32_t* r, uint32_t a) {
    asm volatile("ldmatrix.sync.aligned.m8n8.x2.shared.b16 {%0,%1}, [%2];"
        : "=r"(r[0]), "=r"(r[1]) : "r"(a));
}
__device__ __forceinline__ void mma16(float* c, const uint32_t* a, const uint32_t* b) {
    asm volatile("mma.sync.aligned.m16n8k16.row.col.f32.f16.f16.f32 "
        "{%0,%1,%2,%3}, {%4,%5,%6,%7}, {%8,%9}, {%0,%1,%2,%3};"
        : "+f"(c[0]), "+f"(c[1]), "+f"(c[2]), "+f"(c[3])
        : "r"(a[0]), "r"(a[1]), "r"(a[2]), "r"(a[3]), "r"(b[0]), "r"(b[1]));
}
__device__ __forceinline__ uint2 f4_to_h4(float4 v) {
    __half2 a = __floats2half2_rn(v.x, v.y);
    __half2 b = __floats2half2_rn(v.z, v.w);
    return make_uint2(*(uint32_t*)&a, *(uint32_t*)&b);
}

// ---------------------------------------------------------------------------
// fp16 mma GEMM: C[M,N] = A[M,K] @ B[N,K]^T  (A,B fp16 K-major, BK=32)
// MODE 0: fp32 + bias            MODE 1: half [bh,s,64] + bias
// MODE 2: half vT [bh,d,s]+bias
// ---------------------------------------------------------------------------
template<typename TOUT, int BN, int WM, int WN, int MODE>
__global__ __launch_bounds__(256)
void gemm_h(const __half* __restrict__ A, const __half* __restrict__ B,
            const float* __restrict__ bias, TOUT* __restrict__ C,
            int M, int N, int K)
{
    constexpr int PH   = 40;                 // halves pitch for 32-half row
    constexpr int NWN  = BN / WN;
    constexpr int NMT  = WM / 16, NNT = WN / 8;
    constexpr int ASTG = 128 * PH * 2;       // bytes
    constexpr int BSTG = BN * PH * 2;
    static_assert((128 / WM) * NWN == 8, "warp grid");

    extern __shared__ char smem[];
    const uint32_t sb = smem_u32(smem);
    const int t = threadIdx.x, lane = t & 31, wid = t >> 5;
    const int m0 = blockIdx.y * 128, n0 = blockIdx.x * BN;

    const int wm0 = (wid / NWN) * WM;
    const int wn0 = (wid % NWN) * WN;
    constexpr uint32_t offB = 2 * ASTG;

    float acc[NMT][NNT][4];
    #pragma unroll
    for (int i = 0; i < NMT; i++)
        #pragma unroll
        for (int j = 0; j < NNT; j++)
            #pragma unroll
            for (int q = 0; q < 4; q++) acc[i][j][q] = 0.0f;

    const int NT = K / 32;

    auto issue = [&](int kt, int buf) {
        const int k0 = kt * 32;
        #pragma unroll
        for (int i = 0; i < 2; i++) {            // A: 512 cp16 / 256 thr
            int idx = t + i * 256;
            int row = idx >> 2, seg = idx & 3;
            cp_async16(sb + buf * ASTG + (uint32_t)(row * PH + seg * 8) * 2,
                       A + (long long)(m0 + row) * K + k0 + seg * 8);
        }
        #pragma unroll
        for (int i = 0; i < BN / 64; i++) {      // B: BN*4 cp16 / 256 thr
            int idx = t + i * 256;
            int row = idx >> 2, seg = idx & 3;
            cp_async16(sb + offB + buf * BSTG + (uint32_t)(row * PH + seg * 8) * 2,
                       B + (long long)(n0 + row) * K + k0 + seg * 8);
        }
    };

    issue(0, 0);
    CP_COMMIT();

    for (int kt = 0; kt < NT; kt++) {
        const int buf = kt & 1;
        if (kt + 1 < NT) { issue(kt + 1, buf ^ 1); CP_COMMIT(); CP_WAIT(1); }
        else             { CP_WAIT(0); }
        __syncthreads();

        const uint32_t ab = sb + buf * ASTG;
        const uint32_t bb = sb + offB + buf * BSTG;

        #pragma unroll
        for (int ks = 0; ks < 2; ks++) {
            uint32_t af[NMT][4], bf[NNT][2];
            #pragma unroll
            for (int mt = 0; mt < NMT; mt++)
                ldmx4(af[mt], ab + (uint32_t)((wm0 + mt * 16 + (lane & 15)) * PH
                                              + ks * 16 + (lane >> 4) * 8) * 2);
            #pragma unroll
            for (int nt = 0; nt < NNT; nt++)
                ldmx2(bf[nt], bb + (uint32_t)((wn0 + nt * 8 + (lane & 7)) * PH
                                              + ks * 16 + ((lane >> 3) & 1) * 8) * 2);
            #pragma unroll
            for (int mt = 0; mt < NMT; mt++)
                #pragma unroll
                for (int nt = 0; nt < NNT; nt++)
                    mma16(acc[mt][nt], af[mt], bf[nt]);
        }
        __syncthreads();
    }

    // ---- Epilogue: regs -> padded SMEM (fp32) -> relayout stores ----
    constexpr int EP = BN + 4;
    float* ep = (float*)smem;
    #pragma unroll
    for (int mt = 0; mt < NMT; mt++) {
        #pragma unroll
        for (int nt = 0; nt < NNT; nt++) {
            int r = wm0 + mt * 16 + (lane >> 2);
            int c = wn0 + nt * 8 + (lane & 3) * 2;
            *(float2*)&ep[r * EP + c]       = make_float2(acc[mt][nt][0], acc[mt][nt][1]);
            *(float2*)&ep[(r + 8) * EP + c] = make_float2(acc[mt][nt][2], acc[mt][nt][3]);
        }
    }
    __syncthreads();

    if (MODE == 2) {
        // transposed copy-out: vT[bh, d, s] (half)
        #pragma unroll
        for (int i = 0; i < BN / 8; i++) {
            int col_l = (t >> 5) + 8 * i;
            int sl = (t & 31) * 4;
            float bv = bias[n0 + col_l];
            float4 v;
            v.x = ep[(sl + 0) * EP + col_l] + bv;
            v.y = ep[(sl + 1) * EP + col_l] + bv;
            v.z = ep[(sl + 2) * EP + col_l] + bv;
            v.w = ep[(sl + 3) * EP + col_l] + bv;
            int tok0 = m0 + sl;
            int b = tok0 >> 10, s = tok0 & 1023;
            int colg = n0 + col_l, h = colg >> 6, d = colg & 63;
            *(uint2*)&((__half*)C)[(((long long)(b * NH_ + h)) << 16)
                                   + (long long)d * SEQ_ + s] = f4_to_h4(v);
        }
    } else {
        constexpr int NC4  = BN / 4;
        constexpr int ITER = 128 * NC4 / 256;
        #pragma unroll
        for (int i = 0; i < ITER; i++) {
            int idx = t + i * 256;
            int r_ = idx / NC4, c4 = idx % NC4;
            float4 v = *(float4*)&ep[r_ * EP + 4 * c4];
            int colg = n0 + 4 * c4;
            if (MODE == 0) {
                float4 bv = *(const float4*)&bias[colg];
                v.x += bv.x; v.y += bv.y; v.z += bv.z; v.w += bv.w;
                *(float4*)&((float*)C)[(long long)(m0 + r_) * N + colg] = v;
            } else { // MODE 1
                float4 bv = *(const float4*)&bias[colg];
                v.x += bv.x; v.y += bv.y; v.z += bv.z; v.w += bv.w;
                int tok = m0 + r_, b = tok >> 10, s = tok & 1023;
                int h = colg >> 6, d = colg & 63;
                *(uint2*)&((__half*)C)[(((long long)(b * NH_ + h)) << 16)
                                       + s * DK_ + d] = f4_to_h4(v);
            }
        }
    }
}

// ---------------------------------------------------------------------------
// ctx = attn_w(f32, converted in-flight) @ vT(f16)  -> half ctx [tok, h*64+d]
// BM=128, BN=64, BK=32, K=1024, batched z = bh. 8 warps 32x32.
// A loaded via ld.global.v4 f32 -> cvt h4 -> SMEM (reg-prefetch pipeline).
// ---------------------------------------------------------------------------
__global__ __launch_bounds__(256)
void gemm_ctx_h(const float* __restrict__ P, const __half* __restrict__ vT,
                __half* __restrict__ C)
{
    constexpr int PH   = 40;
    constexpr uint32_t ASTG = 128 * PH * 2;   // 10240 B
    constexpr int NMT = 2, NNT = 4;           // warp tile 32x32

    extern __shared__ char smem[];
    const uint32_t sb = smem_u32(smem);
    const int t = threadIdx.x, lane = t & 31, wid = t >> 5;
    const int bz = blockIdx.z;
    const int m0 = blockIdx.y * 128;

    P  += ((long long)bz) << 20;              // bh * 1024*1024
    vT += ((long long)bz) << 16;              // bh * 64*1024

    const int wm0 = (wid >> 1) * 32;          // 4 warps along m
    const int wn0 = (wid & 1) * 32;           // 2 warps along n

    float acc[NMT][NNT][4];
    #pragma unroll
    for (int i = 0; i < NMT; i++)
        #pragma unroll
        for (int j = 0; j < NNT; j++)
            #pragma unroll
            for (int q = 0; q < 4; q++) acc[i][j][q] = 0.0f;

    // per-thread gmem slices
    const int arow = t >> 3, ac4 = t & 7;     // A: rows 0..31 (+32*i), col4 0..7
    const int brow = t >> 2, bseg = t & 3;    // B: 64 rows x 4 uint4-segs

    float4 ar[4];
    uint4  br;
    auto gload = [&](int kt) {
        const int k0 = kt * 32;
        #pragma unroll
        for (int i = 0; i < 4; i++)
            ar[i] = *(const float4*)(P + (long long)(m0 + arow + i * 32) * 1024
                                     + k0 + ac4 * 4);
        br = *(const uint4*)(vT + (long long)brow * 1024 + k0 + bseg * 8);
    };
    auto sstore = [&]() {
        #pragma unroll
        for (int i = 0; i < 4; i++)
            *(uint2*)(smem + ((uint32_t)((arow + i * 32) * PH + ac4 * 4) * 2))
                = f4_to_h4(ar[i]);
        *(uint4*)(smem + ASTG + ((uint32_t)(brow * PH + bseg * 8) * 2)) = br;
    };

    gload(0);
    for (int kt = 0; kt < 32; kt++) {
        sstore();
        __syncthreads();
        if (kt + 1 < 32) gload(kt + 1);       // overlap gmem with mma

        const uint32_t ab = sb;
        const uint32_t bb = sb + ASTG;
        #pragma unroll
        for (int ks = 0; ks < 2; ks++) {
            uint32_t af[NMT][4], bf[NNT][2];
            #pragma unroll
            for (int mt = 0; mt < NMT; mt++)
                ldmx4(af[mt], ab + (uint32_t)((wm0 + mt * 16 + (lane & 15)) * PH
                                              + ks * 16 + (lane >> 4) * 8) * 2);
            #pragma unroll
            for (int nt = 0; nt < NNT; nt++)
                ldmx2(bf[nt], bb + (uint32_t)((wn0 + nt * 8 + (lane & 7)) * PH
                                              + ks * 16 + ((lane >> 3) & 1) * 8) * 2);
            #pragma unroll
            for (int mt = 0; mt < NMT; mt++)
                #pragma unroll
                for (int nt = 0; nt < NNT; nt++)
                    mma16(acc[mt][nt], af[mt], bf[nt]);
        }
        __syncthreads();
    }

    // epilogue: fp32 SMEM staging -> half ctx
    constexpr int EP = 68;
    float* ep = (float*)smem;
    #pragma unroll
    for (int mt = 0; mt < NMT; mt++) {
        #pragma unroll
        for (int nt = 0; nt < NNT; nt++) {
            int r = wm0 + mt * 16 + (lane >> 2);
            int c = wn0 + nt * 8 + (lane & 3) * 2;
            *(float2*)&ep[r * EP + c]       = make_float2(acc[mt][nt][0], acc[mt][nt][1]);
            *(float2*)&ep[(r + 8) * EP + c] = make_float2(acc[mt][nt][2], acc[mt][nt][3]);
        }
    }
    __syncthreads();

    const int b = bz >> 4, h = bz & 15;
    #pragma unroll
    for (int i = 0; i < 8; i++) {             // 128 rows x 16 col4 / 256 thr
        int idx = t + i * 256;
        int r_ = idx >> 4, c4 = idx & 15;
        float4 v = *(float4*)&ep[r_ * EP + 4 * c4];
        *(uint2*)&C[((long long)(b * SEQ_ + m0 + r_)) * DM_
                    + h * DK_ + 4 * c4] = f4_to_h4(v);
    }
}

// ---------------------------------------------------------------------------
// Fused scores + softmax: one block = 32 q-rows x 1024 k-cols for one bh.
// Writes attn_s (fp32) and attn_w (fp32).
// ---------------------------------------------------------------------------
__global__ __launch_bounds__(256)
void fused_scores(const __half* __restrict__ q, const __half* __restrict__ k,
                  float* __restrict__ attn_s, float* __restrict__ attn_w)
{
    constexpr int PS = 1032;               // S pitch (floats)
    constexpr int PQ = 72;                 // half pitch
    constexpr uint32_t S_BYTES = 32 * PS * 4;        // 132096
    constexpr uint32_t Q_BYTES = 32 * PQ * 2;        // 4608
    constexpr uint32_t KSTG    = 128 * PQ * 2;       // 18432

    extern __shared__ char smem[];
    float* S = (float*)smem;
    const uint32_t sb  = smem_u32(smem);
    const uint32_t qs  = sb + S_BYTES;
    const uint32_t ks0 = qs + Q_BYTES;

    const int t = threadIdx.x, lane = t & 31, w = t >> 5;
    const int bh = blockIdx.y, m0 = blockIdx.x * 32;
    const __half* qg = q + (((long long)bh) << 16) + m0 * 64;
    const __half* kg = k + (((long long)bh) << 16);
    const long long orow = (((long long)bh) << 20) + (long long)m0 * 1024;

    // q tile: 32 rows x 64 halves (one cp16 per thread)
    { int row = t >> 3, seg = t & 7;
      cp_async16(qs + (uint32_t)(row * PQ + seg * 8) * 2, qg + row * 64 + seg * 8); }
    CP_COMMIT();

    auto issueK = [&](int c, int buf) {
        #pragma unroll
        for (int i = 0; i < 4; i++) {
            int idx = t + i * 256;
            int row = idx >> 3, seg = idx & 7;
            cp_async16(ks0 + buf * KSTG + (uint32_t)(row * PQ + seg * 8) * 2,
                       kg + (long long)(c * 128 + row) * 64 + seg * 8);
        }
    };
    issueK(0, 0);
    CP_COMMIT();
    CP_WAIT(1);              // q group done
    __syncthreads();

    // hoist q fragments (K=64 -> 4 k16 steps)
    uint32_t aq[2][4][4];
    #pragma unroll
    for (int mt = 0; mt < 2; mt++)
        #pragma unroll
        for (int ks = 0; ks < 4; ks++)
            ldmx4(aq[mt][ks], qs + (uint32_t)((mt * 16 + (lane & 15)) * PQ
                                              + ks * 16 + (lane >> 4) * 8) * 2);

    for (int c = 0; c < 8; c++) {
        const int buf = c & 1;
        if (c + 1 < 8) { issueK(c + 1, buf ^ 1); CP_COMMIT(); CP_WAIT(1); }
        else           { CP_WAIT(0); }
        __syncthreads();

        float acc[2][2][4] = {};
        const uint32_t kb = ks0 + buf * KSTG;
        #pragma unroll
        for (int ks = 0; ks < 4; ks++) {
            uint32_t bf[2][2];
            #pragma unroll
            for (int nt = 0; nt < 2; nt++)
                ldmx2(bf[nt], kb + (uint32_t)((w * 16 + nt * 8 + (lane & 7)) * PQ
                                              + ks * 16 + ((lane >> 3) & 1) * 8) * 2);
            #pragma unroll
            for (int mt = 0; mt < 2; mt++)
                #pragma unroll
                for (int nt = 0; nt < 2; nt++)
                    mma16(acc[mt][nt], aq[mt][ks], bf[nt]);
        }
        #pragma unroll
        for (int mt = 0; mt < 2; mt++)
            #pragma unroll
            for (int nt = 0; nt < 2; nt++) {
                int r   = mt * 16 + (lane >> 2);
                int col = c * 128 + w * 16 + nt * 8 + (lane & 3) * 2;
                *(float2*)&S[r * PS + col] =
                    make_float2(acc[mt][nt][0] * SCALE_, acc[mt][nt][1] * SCALE_);
                *(float2*)&S[(r + 8) * PS + col] =
                    make_float2(acc[mt][nt][2] * SCALE_, acc[mt][nt][3] * SCALE_);
            }
        __syncthreads();
    }

    // stream attn_s (raw scaled scores)
    #pragma unroll
    for (int i = 0; i < 32; i++) {
        int idx = t + i * 256;
        int r = idx >> 8, c4 = idx & 255;
        *(float4*)&attn_s[orow + r * 1024 + c4 * 4] = *(float4*)&S[r * PS + c4 * 4];
    }

    // softmax: warp w owns rows w*4 .. w*4+3
    for (int rr = 0; rr < 4; rr++) {
        const int r = w * 4 + rr;
        float4 vv[8];
        float m = -1e30f;
        #pragma unroll
        for (int i = 0; i < 8; i++) {
            vv[i] = *(float4*)&S[r * PS + lane * 4 + i * 128];
            m = fmaxf(m, fmaxf(fmaxf(vv[i].x, vv[i].y), fmaxf(vv[i].z, vv[i].w)));
        }
        #pragma unroll
        for (int o = 16; o; o >>= 1) m = fmaxf(m, __shfl_xor_sync(0xffffffffu, m, o));
        float sum = 0.0f;
        #pragma unroll
        for (int i = 0; i < 8; i++) {
            vv[i].x = __expf(vv[i].x - m); vv[i].y = __expf(vv[i].y - m);
            vv[i].z = __expf(vv[i].z - m); vv[i].w = __expf(vv[i].w - m);
            sum += vv[i].x + vv[i].y + vv[i].z + vv[i].w;
        }
        #pragma unroll
        for (int o = 16; o; o >>= 1) sum += __shfl_xor_sync(0xffffffffu, sum, o);
        const float inv = 1.0f / sum;
        const long long rb = orow + (long long)r * 1024;
        #pragma unroll
        for (int i = 0; i < 8; i++) {
            float4 wv = make_float4(vv[i].x * inv, vv[i].y * inv,
                                    vv[i].z * inv, vv[i].w * inv);
            *(float4*)&attn_w[rb + lane * 4 + i * 128] = wv;
        }
    }
}

// ---------------------------------------------------------------------------
// fp32 -> fp16 elementwise (vectorized x4)
// ---------------------------------------------------------------------------
__global__ __launch_bounds__(256)
void f2h(const float* __restrict__ x, __half* __restrict__ y, int n4)
{
    int i = blockIdx.x * 256 + threadIdx.x;
    if (i < n4) ((uint2*)y)[i] = f4_to_h4(((const float4*)x)[i]);
}

// ---------------------------------------------------------------------------
// 1024x1024 transpose + convert to half
// ---------------------------------------------------------------------------
__global__ __launch_bounds__(256)
void transpose_h(const float* __restrict__ W, __half* __restrict__ WT)
{
    __shared__ float tile[32][33];
    int bx = blockIdx.x * 32, by = blockIdx.y * 32;
    int tx = threadIdx.x & 31, ty = threadIdx.x >> 5;
    #pragma unroll
    for (int j = ty; j < 32; j += 8)
        tile[j][tx] = W[(long long)(by + j) * DM_ + bx + tx];
    __syncthreads();
    #pragma unroll
    for (int j = ty; j < 32; j += 8)
        WT[(long long)(bx + j) * DM_ + by + tx] = __float2half(tile[tx][j]);
}

// ---------------------------------------------------------------------------
// Launch
// ---------------------------------------------------------------------------
static constexpr int SMEM_BIG   = 128 * (128 + 4) * 4;                 // 67584
static constexpr int SMEM_CTX   = 128 * 68 * 4;                        // 34816
static constexpr int SMEM_FUSED = 32 * 1032 * 4 + 32 * 72 * 2 + 2 * 128 * 72 * 2; // 173568

extern "C" void kernel_launch(void* const* d_in, const int* in_sizes, int n_in,
                              void* d_out, int out_size)
{
    const float* Q    = (const float*)d_in[0];
    const float* K    = (const float*)d_in[1];
    const float* V    = (const float*)d_in[2];
    const float* WQ_w = (const float*)d_in[3];
    const float* WQ_b = (const float*)d_in[4];
    const float* WK_w = (const float*)d_in[5];
    const float* WK_b = (const float*)d_in[6];
    const float* WV_w = (const float*)d_in[7];
    const float* WV_b = (const float*)d_in[8];
    const float* Wo_w = (const float*)d_in[9];
    const float* Wo_b = (const float*)d_in[10];

    float* out    = (float*)d_out;
    float* attn_w = out    + (long long)TOK_ * DM_;
    float* attn_s = attn_w + (long long)NBH_ * SEQ_ * SEQ_;

    __half *p_Q16, *p_K16, *p_V16, *p_q, *p_k, *p_vT, *p_ctx;
    __half *p_wqT, *p_wkT, *p_wvT, *p_woT;
    cudaGetSymbolAddress((void**)&p_Q16, g_Q16);
    cudaGetSymbolAddress((void**)&p_K16, g_K16);
    cudaGetSymbolAddress((void**)&p_V16, g_V16);
    cudaGetSymbolAddress((void**)&p_q,   g_q);
    cudaGetSymbolAddress((void**)&p_k,   g_k);
    cudaGetSymbolAddress((void**)&p_vT,  g_vT);
    cudaGetSymbolAddress((void**)&p_ctx, g_ctx);
    cudaGetSymbolAddress((void**)&p_wqT, g_wqT);
    cudaGetSymbolAddress((void**)&p_wkT, g_wkT);
    cudaGetSymbolAddress((void**)&p_wvT, g_wvT);
    cudaGetSymbolAddress((void**)&p_woT, g_woT);

    cudaFuncSetAttribute(gemm_h<__half,128,64,32,1>, cudaFuncAttributeMaxDynamicSharedMemorySize, SMEM_BIG);
    cudaFuncSetAttribute(gemm_h<__half,128,64,32,2>, cudaFuncAttributeMaxDynamicSharedMemorySize, SMEM_BIG);
    cudaFuncSetAttribute(gemm_h<float ,128,64,32,0>, cudaFuncAttributeMaxDynamicSharedMemorySize, SMEM_BIG);
    cudaFuncSetAttribute(gemm_ctx_h,   cudaFuncAttributeMaxDynamicSharedMemorySize, SMEM_CTX);
    cudaFuncSetAttribute(fused_scores, cudaFuncAttributeMaxDynamicSharedMemorySize, SMEM_FUSED);

    const int n4 = TOK_ * DM_ / 4;
    dim3 tg(32, 32);

    // Launch order arranged so the ncu capture (-s 5 -c 1 => 6th launch)
    // profiles the Q projection GEMM.
    f2h<<<n4 / 256, 256>>>(Q, p_Q16, n4);                 // 1
    f2h<<<n4 / 256, 256>>>(K, p_K16, n4);                 // 2
    f2h<<<n4 / 256, 256>>>(V, p_V16, n4);                 // 3
    transpose_h<<<tg, 256>>>(WQ_w, p_wqT);                // 4
    transpose_h<<<tg, 256>>>(WK_w, p_wkT);                // 5
    gemm_h<__half,128,64,32,1><<<dim3(8,64,1), 256, SMEM_BIG>>>(   // 6 (captured)
        p_Q16, p_wqT, WQ_b, p_q,  TOK_, DM_, DM_);
    transpose_h<<<tg, 256>>>(WV_w, p_wvT);
    transpose_h<<<tg, 256>>>(Wo_w, p_woT);
    gemm_h<__half,128,64,32,1><<<dim3(8,64,1), 256, SMEM_BIG>>>(
        p_K16, p_wkT, WK_b, p_k,  TOK_, DM_, DM_);
    gemm_h<__half,128,64,32,2><<<dim3(8,64,1), 256, SMEM_BIG>>>(
        p_V16, p_wvT, WV_b, p_vT, TOK_, DM_, DM_);

    // fused scores + softmax (writes attn_s, attn_w)
    fused_scores<<<dim3(32,128), 256, SMEM_FUSED>>>(p_q, p_k, attn_s, attn_w);

    // ctx = attn_w @ vT (fp16 mma, in-flight f32->f16 for A)
    gemm_ctx_h<<<dim3(1,8,128), 256, SMEM_CTX>>>(attn_w, p_vT, p_ctx);

    // output projection (fp32 out + bias)
    gemm_h<float,128,64,32,0><<<dim3(8,64,1), 256, SMEM_BIG>>>(
        p_ctx, p_woT, Wo_b, out, TOK_, DM_, DM_);
}

// round 12
// speedup vs baseline: 4.4100x; 1.0783x over previous
#include <cuda_runtime.h>
#include <cuda_fp16.h>
#include <cstdint>

#define BS_    8
#define SEQ_   1024
#define DM_    1024
#define NH_    16
#define DK_    64
#define NBH_   128
#define TOK_   8192
#define SCALE_ 0.125f

// Scratch (allocation-free rule -> __device__ globals)
__device__ __half g_Q16[TOK_ * DM_];
__device__ __half g_K16[TOK_ * DM_];
__device__ __half g_V16[TOK_ * DM_];
__device__ __half g_q  [NBH_ * SEQ_ * DK_];   // [bh, s, d] fp16
__device__ __half g_k  [NBH_ * SEQ_ * DK_];   // [bh, s, d] fp16
__device__ __half g_vT [NBH_ * DK_ * SEQ_];   // [bh, d, s] fp16
__device__ __half g_ctx[TOK_ * DM_];          // [token, h*64+d] fp16
__device__ __half g_wqT[DM_ * DM_];
__device__ __half g_wkT[DM_ * DM_];
__device__ __half g_wvT[DM_ * DM_];
__device__ __half g_woT[DM_ * DM_];

// ---------------------------------------------------------------------------
// helpers
// ---------------------------------------------------------------------------
__device__ __forceinline__ uint32_t smem_u32(const void* p) {
    uint32_t a;
    asm("{ .reg .u64 t; cvta.to.shared.u64 t, %1; cvt.u32.u64 %0, t; }"
        : "=r"(a) : "l"(p));
    return a;
}
__device__ __forceinline__ void cp_async16(uint32_t s, const void* g) {
    asm volatile("cp.async.cg.shared.global [%0], [%1], 16;" :: "r"(s), "l"(g));
}
#define CP_COMMIT() asm volatile("cp.async.commit_group;" ::: "memory")
#define CP_WAIT(n)  asm volatile("cp.async.wait_group %0;" :: "n"(n) : "memory")

__device__ __forceinline__ void ldmx4(uint32_t* r, uint32_t a) {
    asm volatile("ldmatrix.sync.aligned.m8n8.x4.shared.b16 {%0,%1,%2,%3}, [%4];"
        : "=r"(r[0]), "=r"(r[1]), "=r"(r[2]), "=r"(r[3]) : "r"(a));
}
__device__ __forceinline__ void ldmx2(uint32_t* r, uint32_t a) {
    asm volatile("ldmatrix.sync.aligned.m8n8.x2.shared.b16 {%0,%1}, [%2];"
        : "=r"(r[0]), "=r"(r[1]) : "r"(a));
}
__device__ __forceinline__ void mma16(float* c, const uint32_t* a, const uint32_t* b) {
    asm volatile("mma.sync.aligned.m16n8k16.row.col.f32.f16.f16.f32 "
        "{%0,%1,%2,%3}, {%4,%5,%6,%7}, {%8,%9}, {%0,%1,%2,%3};"
        : "+f"(c[0]), "+f"(c[1]), "+f"(c[2]), "+f"(c[3])
        : "r"(a[0]), "r"(a[1]), "r"(a[2]), "r"(a[3]), "r"(b[0]), "r"(b[1]));
}
__device__ __forceinline__ uint2 f4_to_h4(float4 v) {
    __half2 a = __floats2half2_rn(v.x, v.y);
    __half2 b = __floats2half2_rn(v.z, v.w);
    return make_uint2(*(uint32_t*)&a, *(uint32_t*)&b);
}

// ---------------------------------------------------------------------------
// fp16 mma GEMM: C[M,N] = A[M,K] @ B[N,K]^T  (A,B fp16 K-major, BK=32)
// MODE 0: fp32 + bias            MODE 1: half [bh,s,64] + bias
// MODE 2: half vT [bh,d,s]+bias
// ---------------------------------------------------------------------------
template<typename TOUT, int BN, int WM, int WN, int MODE>
__global__ __launch_bounds__(256)
void gemm_h(const __half* __restrict__ A, const __half* __restrict__ B,
            const float* __restrict__ bias, TOUT* __restrict__ C,
            int M, int N, int K)
{
    constexpr int PH   = 40;                 // halves pitch for 32-half row
    constexpr int NWN  = BN / WN;
    constexpr int NMT  = WM / 16, NNT = WN / 8;
    constexpr int ASTG = 128 * PH * 2;       // bytes
    constexpr int BSTG = BN * PH * 2;
    static_assert((128 / WM) * NWN == 8, "warp grid");

    extern __shared__ char smem[];
    const uint32_t sb = smem_u32(smem);
    const int t = threadIdx.x, lane = t & 31, wid = t >> 5;
    const int m0 = blockIdx.y * 128, n0 = blockIdx.x * BN;

    const int wm0 = (wid / NWN) * WM;
    const int wn0 = (wid % NWN) * WN;
    constexpr uint32_t offB = 2 * ASTG;

    float acc[NMT][NNT][4];
    #pragma unroll
    for (int i = 0; i < NMT; i++)
        #pragma unroll
        for (int j = 0; j < NNT; j++)
            #pragma unroll
            for (int q = 0; q < 4; q++) acc[i][j][q] = 0.0f;

    const int NT = K / 32;

    auto issue = [&](int kt, int buf) {
        const int k0 = kt * 32;
        #pragma unroll
        for (int i = 0; i < 2; i++) {            // A: 512 cp16 / 256 thr
            int idx = t + i * 256;
            int row = idx >> 2, seg = idx & 3;
            cp_async16(sb + buf * ASTG + (uint32_t)(row * PH + seg * 8) * 2,
                       A + (long long)(m0 + row) * K + k0 + seg * 8);
        }
        #pragma unroll
        for (int i = 0; i < BN / 64; i++) {      // B: BN*4 cp16 / 256 thr
            int idx = t + i * 256;
            int row = idx >> 2, seg = idx & 3;
            cp_async16(sb + offB + buf * BSTG + (uint32_t)(row * PH + seg * 8) * 2,
                       B + (long long)(n0 + row) * K + k0 + seg * 8);
        }
    };

    issue(0, 0);
    CP_COMMIT();

    for (int kt = 0; kt < NT; kt++) {
        const int buf = kt & 1;
        if (kt + 1 < NT) { issue(kt + 1, buf ^ 1); CP_COMMIT(); CP_WAIT(1); }
        else             { CP_WAIT(0); }
        __syncthreads();

        const uint32_t ab = sb + buf * ASTG;
        const uint32_t bb = sb + offB + buf * BSTG;

        #pragma unroll
        for (int ks = 0; ks < 2; ks++) {
            uint32_t af[NMT][4], bf[NNT][2];
            #pragma unroll
            for (int mt = 0; mt < NMT; mt++)
                ldmx4(af[mt], ab + (uint32_t)((wm0 + mt * 16 + (lane & 15)) * PH
                                              + ks * 16 + (lane >> 4) * 8) * 2);
            #pragma unroll
            for (int nt = 0; nt < NNT; nt++)
                ldmx2(bf[nt], bb + (uint32_t)((wn0 + nt * 8 + (lane & 7)) * PH
                                              + ks * 16 + ((lane >> 3) & 1) * 8) * 2);
            #pragma unroll
            for (int mt = 0; mt < NMT; mt++)
                #pragma unroll
                for (int nt = 0; nt < NNT; nt++)
                    mma16(acc[mt][nt], af[mt], bf[nt]);
        }
        __syncthreads();
    }

    // ---- Epilogue: regs -> padded SMEM (fp32) -> relayout stores ----
    constexpr int EP = BN + 4;
    float* ep = (float*)smem;
    #pragma unroll
    for (int mt = 0; mt < NMT; mt++) {
        #pragma unroll
        for (int nt = 0; nt < NNT; nt++) {
            int r = wm0 + mt * 16 + (lane >> 2);
            int c = wn0 + nt * 8 + (lane & 3) * 2;
            *(float2*)&ep[r * EP + c]       = make_float2(acc[mt][nt][0], acc[mt][nt][1]);
            *(float2*)&ep[(r + 8) * EP + c] = make_float2(acc[mt][nt][2], acc[mt][nt][3]);
        }
    }
    __syncthreads();

    if (MODE == 2) {
        // transposed copy-out: vT[bh, d, s] (half)
        #pragma unroll
        for (int i = 0; i < BN / 8; i++) {
            int col_l = (t >> 5) + 8 * i;
            int sl = (t & 31) * 4;
            float bv = bias[n0 + col_l];
            float4 v;
            v.x = ep[(sl + 0) * EP + col_l] + bv;
            v.y = ep[(sl + 1) * EP + col_l] + bv;
            v.z = ep[(sl + 2) * EP + col_l] + bv;
            v.w = ep[(sl + 3) * EP + col_l] + bv;
            int tok0 = m0 + sl;
            int b = tok0 >> 10, s = tok0 & 1023;
            int colg = n0 + col_l, h = colg >> 6, d = colg & 63;
            *(uint2*)&((__half*)C)[(((long long)(b * NH_ + h)) << 16)
                                   + (long long)d * SEQ_ + s] = f4_to_h4(v);
        }
    } else {
        constexpr int NC4  = BN / 4;
        constexpr int ITER = 128 * NC4 / 256;
        #pragma unroll
        for (int i = 0; i < ITER; i++) {
            int idx = t + i * 256;
            int r_ = idx / NC4, c4 = idx % NC4;
            float4 v = *(float4*)&ep[r_ * EP + 4 * c4];
            int colg = n0 + 4 * c4;
            if (MODE == 0) {
                float4 bv = *(const float4*)&bias[colg];
                v.x += bv.x; v.y += bv.y; v.z += bv.z; v.w += bv.w;
                *(float4*)&((float*)C)[(long long)(m0 + r_) * N + colg] = v;
            } else { // MODE 1
                float4 bv = *(const float4*)&bias[colg];
                v.x += bv.x; v.y += bv.y; v.z += bv.z; v.w += bv.w;
                int tok = m0 + r_, b = tok >> 10, s = tok & 1023;
                int h = colg >> 6, d = colg & 63;
                *(uint2*)&((__half*)C)[(((long long)(b * NH_ + h)) << 16)
                                       + s * DK_ + d] = f4_to_h4(v);
            }
        }
    }
}

// ---------------------------------------------------------------------------
// Fully fused attention: scores (QK^T) + softmax + ctx (P @ V).
// One block = 32 q-rows x 1024 k-cols for one bh.
// Phase 1: QK mma -> attn_s fp32 (direct from regs) + S16 fp16 in SMEM
// Phase 2: softmax on S16 -> attn_w fp32 + S16 := P (fp16, in place)
// Phase 3: ctx = S16 @ vT (vT streamed, L2-resident per bh) -> half g_ctx
// ---------------------------------------------------------------------------
__global__ __launch_bounds__(256)
void fused_attn(const __half* __restrict__ q, const __half* __restrict__ k,
                const __half* __restrict__ vT,
                float* __restrict__ attn_s, float* __restrict__ attn_w,
                __half* __restrict__ ctx)
{
    constexpr int P16 = 1032;                         // S16 pitch (halves)
    constexpr uint32_t S16B  = 32u * P16 * 2;         // 66048
    constexpr int PQ = 72;
    constexpr uint32_t Q_OFF = S16B;                  // 4608 bytes (q / ctx stage)
    constexpr uint32_t K_OFF = Q_OFF + 4608;          // k / v stages
    constexpr uint32_t KSTG  = 128 * PQ * 2;          // 18432
    constexpr int PV = 40;
    constexpr uint32_t VSTG  = 64 * PV * 2;           // 5120

    extern __shared__ char smem[];
    const uint32_t sb = smem_u32(smem);
    const int t = threadIdx.x, lane = t & 31, w = t >> 5;
    const int bh = blockIdx.y, m0 = blockIdx.x * 32;
    const __half* qg = q  + (((long long)bh) << 16) + m0 * 64;
    const __half* kg = k  + (((long long)bh) << 16);
    const __half* vg = vT + (((long long)bh) << 16);
    const long long orow = (((long long)bh) << 20) + (long long)m0 * 1024;

    // ---- Phase 1: QK^T ----
    { int row = t >> 3, seg = t & 7;
      cp_async16(sb + Q_OFF + (uint32_t)(row * PQ + seg * 8) * 2,
                 qg + row * 64 + seg * 8); }
    CP_COMMIT();

    auto issueK = [&](int c, int buf) {
        #pragma unroll
        for (int i = 0; i < 4; i++) {
            int idx = t + i * 256;
            int row = idx >> 3, seg = idx & 7;
            cp_async16(sb + K_OFF + buf * KSTG + (uint32_t)(row * PQ + seg * 8) * 2,
                       kg + (long long)(c * 128 + row) * 64 + seg * 8);
        }
    };
    issueK(0, 0);
    CP_COMMIT();
    CP_WAIT(1);
    __syncthreads();

    uint32_t aq[2][4][4];
    #pragma unroll
    for (int mt = 0; mt < 2; mt++)
        #pragma unroll
        for (int ks = 0; ks < 4; ks++)
            ldmx4(aq[mt][ks], sb + Q_OFF + (uint32_t)((mt * 16 + (lane & 15)) * PQ
                                                      + ks * 16 + (lane >> 4) * 8) * 2);

    for (int c = 0; c < 8; c++) {
        const int buf = c & 1;
        if (c + 1 < 8) { issueK(c + 1, buf ^ 1); CP_COMMIT(); CP_WAIT(1); }
        else           { CP_WAIT(0); }
        __syncthreads();

        float acc[2][2][4] = {};
        const uint32_t kb = sb + K_OFF + buf * KSTG;
        #pragma unroll
        for (int ks = 0; ks < 4; ks++) {
            uint32_t bf[2][2];
            #pragma unroll
            for (int nt = 0; nt < 2; nt++)
                ldmx2(bf[nt], kb + (uint32_t)((w * 16 + nt * 8 + (lane & 7)) * PQ
                                              + ks * 16 + ((lane >> 3) & 1) * 8) * 2);
            #pragma unroll
            for (int mt = 0; mt < 2; mt++)
                #pragma unroll
                for (int nt = 0; nt < 2; nt++)
                    mma16(acc[mt][nt], aq[mt][ks], bf[nt]);
        }
        // epilogue: stream attn_s direct (full 32B sectors) + S16 fp16 copy
        #pragma unroll
        for (int mt = 0; mt < 2; mt++)
            #pragma unroll
            for (int nt = 0; nt < 2; nt++) {
                int r   = mt * 16 + (lane >> 2);
                int col = c * 128 + w * 16 + nt * 8 + (lane & 3) * 2;
                float2 v0 = make_float2(acc[mt][nt][0] * SCALE_, acc[mt][nt][1] * SCALE_);
                float2 v1 = make_float2(acc[mt][nt][2] * SCALE_, acc[mt][nt][3] * SCALE_);
                *(float2*)&attn_s[orow + (long long)r * 1024 + col]       = v0;
                *(float2*)&attn_s[orow + (long long)(r + 8) * 1024 + col] = v1;
                *(__half2*)(smem + (uint32_t)(r * P16 + col) * 2)
                    = __floats2half2_rn(v0.x, v0.y);
                *(__half2*)(smem + (uint32_t)((r + 8) * P16 + col) * 2)
                    = __floats2half2_rn(v1.x, v1.y);
            }
        __syncthreads();
    }

    // prefetch vT tile 0 (overlaps softmax)
    { int row = t >> 2, seg = t & 3;
      cp_async16(sb + K_OFF + (uint32_t)(row * PV + seg * 8) * 2,
                 vg + (long long)row * 1024 + seg * 8); }
    CP_COMMIT();

    // ---- Phase 2: softmax (warp w owns rows w*4..w*4+3, row-exclusive) ----
    for (int rr = 0; rr < 4; rr++) {
        const int r = w * 4 + rr;
        float4 vv[8];
        float m = -1e30f;
        #pragma unroll
        for (int i = 0; i < 8; i++) {
            uint2 u = *(uint2*)(smem + (uint32_t)(r * P16 + lane * 4 + i * 128) * 2);
            float2 f0 = __half22float2(*(__half2*)&u.x);
            float2 f1 = __half22float2(*(__half2*)&u.y);
            vv[i] = make_float4(f0.x, f0.y, f1.x, f1.y);
            m = fmaxf(m, fmaxf(fmaxf(vv[i].x, vv[i].y), fmaxf(vv[i].z, vv[i].w)));
        }
        #pragma unroll
        for (int o = 16; o; o >>= 1) m = fmaxf(m, __shfl_xor_sync(0xffffffffu, m, o));
        float sum = 0.0f;
        #pragma unroll
        for (int i = 0; i < 8; i++) {
            vv[i].x = __expf(vv[i].x - m); vv[i].y = __expf(vv[i].y - m);
            vv[i].z = __expf(vv[i].z - m); vv[i].w = __expf(vv[i].w - m);
            sum += vv[i].x + vv[i].y + vv[i].z + vv[i].w;
        }
        #pragma unroll
        for (int o = 16; o; o >>= 1) sum += __shfl_xor_sync(0xffffffffu, sum, o);
        const float inv = 1.0f / sum;
        const long long rb = orow + (long long)r * 1024;
        #pragma unroll
        for (int i = 0; i < 8; i++) {
            float4 wv = make_float4(vv[i].x * inv, vv[i].y * inv,
                                    vv[i].z * inv, vv[i].w * inv);
            *(float4*)&attn_w[rb + lane * 4 + i * 128] = wv;
            uint2 u;
            *(__half2*)&u.x = __floats2half2_rn(wv.x, wv.y);
            *(__half2*)&u.y = __floats2half2_rn(wv.z, wv.w);
            *(uint2*)(smem + (uint32_t)(r * P16 + lane * 4 + i * 128) * 2) = u;
        }
    }
    __syncthreads();

    // ---- Phase 3: ctx = P(S16) @ vT^T  (C 32x64) ----
    auto issueV = [&](int kt, int buf) {
        int row = t >> 2, seg = t & 3;
        cp_async16(sb + K_OFF + buf * VSTG + (uint32_t)(row * PV + seg * 8) * 2,
                   vg + (long long)row * 1024 + kt * 32 + seg * 8);
    };

    const int wm = (w >> 2) * 16;          // 2 warps along m
    const int wn = (w & 3) * 16;           // 4 warps along n
    float acc3[2][4] = {};

    for (int kt = 0; kt < 32; kt++) {
        const int buf = kt & 1;
        if (kt + 1 < 32) { issueV(kt + 1, buf ^ 1); CP_COMMIT(); CP_WAIT(1); }
        else             { CP_WAIT(0); }
        __syncthreads();

        const uint32_t vb = sb + K_OFF + buf * VSTG;
        #pragma unroll
        for (int ks = 0; ks < 2; ks++) {
            uint32_t af[4], bf[2][2];
            ldmx4(af, sb + (uint32_t)((wm + (lane & 15)) * P16
                                      + kt * 32 + ks * 16 + (lane >> 4) * 8) * 2);
            #pragma unroll
            for (int nt = 0; nt < 2; nt++)
                ldmx2(bf[nt], vb + (uint32_t)((wn + nt * 8 + (lane & 7)) * PV
                                              + ks * 16 + ((lane >> 3) & 1) * 8) * 2);
            #pragma unroll
            for (int nt = 0; nt < 2; nt++)
                mma16(acc3[nt], af, bf[nt]);
        }
        __syncthreads();
    }

    // ctx epilogue: fp16 stage (Q_OFF area, pitch 68 halves) -> coalesced gmem
    #pragma unroll
    for (int nt = 0; nt < 2; nt++) {
        int r  = lane >> 2;
        int cc = wn + nt * 8 + (lane & 3) * 2;
        *(__half2*)(smem + Q_OFF + (uint32_t)((wm + r) * 68 + cc) * 2)
            = __floats2half2_rn(acc3[nt][0], acc3[nt][1]);
        *(__half2*)(smem + Q_OFF + (uint32_t)((wm + r + 8) * 68 + cc) * 2)
            = __floats2half2_rn(acc3[nt][2], acc3[nt][3]);
    }
    __syncthreads();

    const int b = bh >> 4, h = bh & 15;
    #pragma unroll
    for (int i = 0; i < 2; i++) {
        int idx = t + i * 256;
        int row = idx >> 4, seg = idx & 15;
        uint2 u = *(uint2*)(smem + Q_OFF + (uint32_t)(row * 68 + seg * 4) * 2);
        *(uint2*)&ctx[((long long)(b * SEQ_ + m0 + row)) * DM_ + h * DK_ + seg * 4] = u;
    }
}

// ---------------------------------------------------------------------------
// fp32 -> fp16 elementwise (vectorized x4)
// ---------------------------------------------------------------------------
__global__ __launch_bounds__(256)
void f2h(const float* __restrict__ x, __half* __restrict__ y, int n4)
{
    int i = blockIdx.x * 256 + threadIdx.x;
    if (i < n4) ((uint2*)y)[i] = f4_to_h4(((const float4*)x)[i]);
}

// ---------------------------------------------------------------------------
// 1024x1024 transpose + convert to half
// ---------------------------------------------------------------------------
__global__ __launch_bounds__(256)
void transpose_h(const float* __restrict__ W, __half* __restrict__ WT)
{
    __shared__ float tile[32][33];
    int bx = blockIdx.x * 32, by = blockIdx.y * 32;
    int tx = threadIdx.x & 31, ty = threadIdx.x >> 5;
    #pragma unroll
    for (int j = ty; j < 32; j += 8)
        tile[j][tx] = W[(long long)(by + j) * DM_ + bx + tx];
    __syncthreads();
    #pragma unroll
    for (int j = ty; j < 32; j += 8)
        WT[(long long)(bx + j) * DM_ + by + tx] = __float2half(tile[tx][j]);
}

// ---------------------------------------------------------------------------
// Launch
// ---------------------------------------------------------------------------
static constexpr int SMEM_BIG   = 128 * (128 + 4) * 4;            // 67584
static constexpr int SMEM_FUSED = 32 * 1032 * 2 + 4608 + 2 * 128 * 72 * 2; // 107520

extern "C" void kernel_launch(void* const* d_in, const int* in_sizes, int n_in,
                              void* d_out, int out_size)
{
    const float* Q    = (const float*)d_in[0];
    const float* K    = (const float*)d_in[1];
    const float* V    = (const float*)d_in[2];
    const float* WQ_w = (const float*)d_in[3];
    const float* WQ_b = (const float*)d_in[4];
    const float* WK_w = (const float*)d_in[5];
    const float* WK_b = (const float*)d_in[6];
    const float* WV_w = (const float*)d_in[7];
    const float* WV_b = (const float*)d_in[8];
    const float* Wo_w = (const float*)d_in[9];
    const float* Wo_b = (const float*)d_in[10];

    float* out    = (float*)d_out;
    float* attn_w = out    + (long long)TOK_ * DM_;
    float* attn_s = attn_w + (long long)NBH_ * SEQ_ * SEQ_;

    __half *p_Q16, *p_K16, *p_V16, *p_q, *p_k, *p_vT, *p_ctx;
    __half *p_wqT, *p_wkT, *p_wvT, *p_woT;
    cudaGetSymbolAddress((void**)&p_Q16, g_Q16);
    cudaGetSymbolAddress((void**)&p_K16, g_K16);
    cudaGetSymbolAddress((void**)&p_V16, g_V16);
    cudaGetSymbolAddress((void**)&p_q,   g_q);
    cudaGetSymbolAddress((void**)&p_k,   g_k);
    cudaGetSymbolAddress((void**)&p_vT,  g_vT);
    cudaGetSymbolAddress((void**)&p_ctx, g_ctx);
    cudaGetSymbolAddress((void**)&p_wqT, g_wqT);
    cudaGetSymbolAddress((void**)&p_wkT, g_wkT);
    cudaGetSymbolAddress((void**)&p_wvT, g_wvT);
    cudaGetSymbolAddress((void**)&p_woT, g_woT);

    cudaFuncSetAttribute(gemm_h<__half,128,64,32,1>, cudaFuncAttributeMaxDynamicSharedMemorySize, SMEM_BIG);
    cudaFuncSetAttribute(gemm_h<__half,128,64,32,2>, cudaFuncAttributeMaxDynamicSharedMemorySize, SMEM_BIG);
    cudaFuncSetAttribute(gemm_h<float ,128,64,32,0>, cudaFuncAttributeMaxDynamicSharedMemorySize, SMEM_BIG);
    cudaFuncSetAttribute(fused_attn, cudaFuncAttributeMaxDynamicSharedMemorySize, SMEM_FUSED);

    const int n4 = TOK_ * DM_ / 4;
    dim3 tg(32, 32);

    f2h<<<n4 / 256, 256>>>(Q, p_Q16, n4);
    f2h<<<n4 / 256, 256>>>(K, p_K16, n4);
    f2h<<<n4 / 256, 256>>>(V, p_V16, n4);
    transpose_h<<<tg, 256>>>(WQ_w, p_wqT);
    transpose_h<<<tg, 256>>>(WK_w, p_wkT);
    gemm_h<__half,128,64,32,1><<<dim3(8,64,1), 256, SMEM_BIG>>>(
        p_Q16, p_wqT, WQ_b, p_q,  TOK_, DM_, DM_);
    transpose_h<<<tg, 256>>>(WV_w, p_wvT);
    transpose_h<<<tg, 256>>>(Wo_w, p_woT);
    gemm_h<__half,128,64,32,1><<<dim3(8,64,1), 256, SMEM_BIG>>>(
        p_K16, p_wkT, WK_b, p_k,  TOK_, DM_, DM_);
    gemm_h<__half,128,64,32,2><<<dim3(8,64,1), 256, SMEM_BIG>>>(
        p_V16, p_wvT, WV_b, p_vT, TOK_, DM_, DM_);

    // fully fused attention (scores + softmax + ctx)
    fused_attn<<<dim3(32,128), 256, SMEM_FUSED>>>(
        p_q, p_k, p_vT, attn_s, attn_w, p_ctx);

    // output projection (fp32 out + bias)
    gemm_h<float,128,64,32,0><<<dim3(8,64,1), 256, SMEM_BIG>>>(
        p_ctx, p_woT, Wo_b, out, TOK_, DM_, DM_);
}

// round 15
// speedup vs baseline: 5.2066x; 1.1806x over previous
#include <cuda_runtime.h>
#include <cuda_fp16.h>
#include <cstdint>

#define BS_    8
#define SEQ_   1024
#define DM_    1024
#define NH_    16
#define DK_    64
#define NBH_   128
#define TOK_   8192
#define SCALE_ 0.125f

// Scratch (allocation-free rule -> __device__ globals)
__device__ __half g_Q16[TOK_ * DM_];
__device__ __half g_K16[TOK_ * DM_];
__device__ __half g_V16[TOK_ * DM_];
__device__ __half g_q  [NBH_ * SEQ_ * DK_];   // [bh, s, d] fp16
__device__ __half g_k  [NBH_ * SEQ_ * DK_];   // [bh, s, d] fp16
__device__ __half g_vT [NBH_ * DK_ * SEQ_];   // [bh, d, s] fp16
__device__ __half g_ctx[TOK_ * DM_];          // [token, h*64+d] fp16
__device__ __half g_wqT[DM_ * DM_];
__device__ __half g_wkT[DM_ * DM_];
__device__ __half g_wvT[DM_ * DM_];
__device__ __half g_woT[DM_ * DM_];

// ---------------------------------------------------------------------------
// helpers
// ---------------------------------------------------------------------------
__device__ __forceinline__ uint32_t smem_u32(const void* p) {
    uint32_t a;
    asm("{ .reg .u64 t; cvta.to.shared.u64 t, %1; cvt.u32.u64 %0, t; }"
        : "=r"(a) : "l"(p));
    return a;
}
__device__ __forceinline__ void cp_async16(uint32_t s, const void* g) {
    asm volatile("cp.async.cg.shared.global [%0], [%1], 16;" :: "r"(s), "l"(g));
}
#define CP_COMMIT() asm volatile("cp.async.commit_group;" ::: "memory")
#define CP_WAIT(n)  asm volatile("cp.async.wait_group %0;" :: "n"(n) : "memory")

__device__ __forceinline__ void ldmx4(uint32_t* r, uint32_t a) {
    asm volatile("ldmatrix.sync.aligned.m8n8.x4.shared.b16 {%0,%1,%2,%3}, [%4];"
        : "=r"(r[0]), "=r"(r[1]), "=r"(r[2]), "=r"(r[3]) : "r"(a));
}
__device__ __forceinline__ void ldmx2(uint32_t* r, uint32_t a) {
    asm volatile("ldmatrix.sync.aligned.m8n8.x2.shared.b16 {%0,%1}, [%2];"
        : "=r"(r[0]), "=r"(r[1]) : "r"(a));
}
__device__ __forceinline__ void mma16(float* c, const uint32_t* a, const uint32_t* b) {
    asm volatile("mma.sync.aligned.m16n8k16.row.col.f32.f16.f16.f32 "
        "{%0,%1,%2,%3}, {%4,%5,%6,%7}, {%8,%9}, {%0,%1,%2,%3};"
        : "+f"(c[0]), "+f"(c[1]), "+f"(c[2]), "+f"(c[3])
        : "r"(a[0]), "r"(a[1]), "r"(a[2]), "r"(a[3]), "r"(b[0]), "r"(b[1]));
}
__device__ __forceinline__ uint2 f4_to_h4(float4 v) {
    __half2 a = __floats2half2_rn(v.x, v.y);
    __half2 b = __floats2half2_rn(v.z, v.w);
    return make_uint2(*(uint32_t*)&a, *(uint32_t*)&b);
}

// ---------------------------------------------------------------------------
// fp16 mma GEMM: C[M,N] = A[M,K] @ B[N,K]^T  (A,B fp16 K-major, BK=32)
// 3-stage cp.async pipeline, ONE __syncthreads per k-iter.
// MODE 0: fp32 + bias            MODE 1: half [bh,s,64] + bias
// MODE 2: half vT [bh,d,s]+bias
// ---------------------------------------------------------------------------
template<typename TOUT, int BN, int WM, int WN, int MODE>
__global__ __launch_bounds__(256, 2)
void gemm_h(const __half* __restrict__ A, const __half* __restrict__ B,
            const float* __restrict__ bias, TOUT* __restrict__ C,
            int M, int N, int K)
{
    constexpr int PH   = 40;                 // halves pitch for 32-half row
    constexpr int NWN  = BN / WN;
    constexpr int NMT  = WM / 16, NNT = WN / 8;
    constexpr int ASTG = 128 * PH * 2;       // bytes
    constexpr int BSTG = BN * PH * 2;
    constexpr int STG  = ASTG + BSTG;        // one stage (A then B)
    static_assert((128 / WM) * NWN == 8, "warp grid");

    extern __shared__ char smem[];
    const uint32_t sb = smem_u32(smem);
    const int t = threadIdx.x, lane = t & 31, wid = t >> 5;
    const int m0 = blockIdx.y * 128, n0 = blockIdx.x * BN;

    const int wm0 = (wid / NWN) * WM;
    const int wn0 = (wid % NWN) * WN;

    float acc[NMT][NNT][4];
    #pragma unroll
    for (int i = 0; i < NMT; i++)
        #pragma unroll
        for (int j = 0; j < NNT; j++)
            #pragma unroll
            for (int q = 0; q < 4; q++) acc[i][j][q] = 0.0f;

    const int NT = K / 32;

    auto issue = [&](int kt, int slot) {
        const int k0 = kt * 32;
        const uint32_t base = sb + slot * STG;
        #pragma unroll
        for (int i = 0; i < 2; i++) {            // A: 512 cp16 / 256 thr
            int idx = t + i * 256;
            int row = idx >> 2, seg = idx & 3;
            cp_async16(base + (uint32_t)(row * PH + seg * 8) * 2,
                       A + (long long)(m0 + row) * K + k0 + seg * 8);
        }
        #pragma unroll
        for (int i = 0; i < BN / 64; i++) {      // B: BN*4 cp16 / 256 thr
            int idx = t + i * 256;
            int row = idx >> 2, seg = idx & 3;
            cp_async16(base + ASTG + (uint32_t)(row * PH + seg * 8) * 2,
                       B + (long long)(n0 + row) * K + k0 + seg * 8);
        }
    };

    issue(0, 0); CP_COMMIT();
    issue(1, 1); CP_COMMIT();

    for (int kt = 0; kt < NT; kt++) {
        if (kt + 1 < NT) { CP_WAIT(1); } else { CP_WAIT(0); }
        __syncthreads();

        const uint32_t ab = sb + (kt % 3) * STG;
        const uint32_t bb = ab + ASTG;

        #pragma unroll
        for (int ks = 0; ks < 2; ks++) {
            uint32_t af[NMT][4], bf[NNT][2];
            #pragma unroll
            for (int mt = 0; mt < NMT; mt++)
                ldmx4(af[mt], ab + (uint32_t)((wm0 + mt * 16 + (lane & 15)) * PH
                                              + ks * 16 + (lane >> 4) * 8) * 2);
            #pragma unroll
            for (int nt = 0; nt < NNT; nt++)
                ldmx2(bf[nt], bb + (uint32_t)((wn0 + nt * 8 + (lane & 7)) * PH
                                              + ks * 16 + ((lane >> 3) & 1) * 8) * 2);
            #pragma unroll
            for (int mt = 0; mt < NMT; mt++)
                #pragma unroll
                for (int nt = 0; nt < NNT; nt++)
                    mma16(acc[mt][nt], af[mt], bf[nt]);
        }
        if (kt + 2 < NT) { issue(kt + 2, (kt + 2) % 3); CP_COMMIT(); }
    }
    __syncthreads();

    // ---- Epilogue: regs -> padded SMEM (fp32) -> relayout stores ----
    constexpr int EP = BN + 4;
    float* ep = (float*)smem;
    #pragma unroll
    for (int mt = 0; mt < NMT; mt++) {
        #pragma unroll
        for (int nt = 0; nt < NNT; nt++) {
            int r = wm0 + mt * 16 + (lane >> 2);
            int c = wn0 + nt * 8 + (lane & 3) * 2;
            *(float2*)&ep[r * EP + c]       = make_float2(acc[mt][nt][0], acc[mt][nt][1]);
            *(float2*)&ep[(r + 8) * EP + c] = make_float2(acc[mt][nt][2], acc[mt][nt][3]);
        }
    }
    __syncthreads();

    if (MODE == 2) {
        // transposed copy-out: vT[bh, d, s] (half)
        #pragma unroll
        for (int i = 0; i < BN / 8; i++) {
            int col_l = (t >> 5) + 8 * i;
            int sl = (t & 31) * 4;
            float bv = bias[n0 + col_l];
            float4 v;
            v.x = ep[(sl + 0) * EP + col_l] + bv;
            v.y = ep[(sl + 1) * EP + col_l] + bv;
            v.z = ep[(sl + 2) * EP + col_l] + bv;
            v.w = ep[(sl + 3) * EP + col_l] + bv;
            int tok0 = m0 + sl;
            int b = tok0 >> 10, s = tok0 & 1023;
            int colg = n0 + col_l, h = colg >> 6, d = colg & 63;
            *(uint2*)&((__half*)C)[(((long long)(b * NH_ + h)) << 16)
                                   + (long long)d * SEQ_ + s] = f4_to_h4(v);
        }
    } else {
        constexpr int NC4  = BN / 4;
        constexpr int ITER = 128 * NC4 / 256;
        #pragma unroll
        for (int i = 0; i < ITER; i++) {
            int idx = t + i * 256;
            int r_ = idx / NC4, c4 = idx % NC4;
            float4 v = *(float4*)&ep[r_ * EP + 4 * c4];
            int colg = n0 + 4 * c4;
            if (MODE == 0) {
                float4 bv = *(const float4*)&bias[colg];
                v.x += bv.x; v.y += bv.y; v.z += bv.z; v.w += bv.w;
                *(float4*)&((float*)C)[(long long)(m0 + r_) * N + colg] = v;
            } else { // MODE 1
                float4 bv = *(const float4*)&bias[colg];
                v.x += bv.x; v.y += bv.y; v.z += bv.z; v.w += bv.w;
                int tok = m0 + r_, b = tok >> 10, s = tok & 1023;
                int h = colg >> 6, d = colg & 63;
                *(uint2*)&((__half*)C)[(((long long)(b * NH_ + h)) << 16)
                                       + s * DK_ + d] = f4_to_h4(v);
            }
        }
    }
}

// ---------------------------------------------------------------------------
// Fully fused attention: scores (QK^T) + softmax + ctx (P @ V).
// One block = 32 q-rows x 1024 k-cols for one bh.
// Phase 3 now: 16 iters of 64-wide V chunks, 3-stage, 1 sync/iter.
// ---------------------------------------------------------------------------
__global__ __launch_bounds__(256)
void fused_attn(const __half* __restrict__ q, const __half* __restrict__ k,
                const __half* __restrict__ vT,
                float* __restrict__ attn_s, float* __restrict__ attn_w,
                __half* __restrict__ ctx)
{
    constexpr int P16 = 1032;                         // S16 pitch (halves)
    constexpr uint32_t S16B  = 32u * P16 * 2;         // 66048
    constexpr int PQ = 72;
    constexpr uint32_t Q_OFF = S16B;                  // 4608 bytes (q / ctx stage)
    constexpr uint32_t K_OFF = Q_OFF + 4608;          // k / v stages
    constexpr uint32_t KSTG  = 128 * PQ * 2;          // 18432
    constexpr int PV = 72;
    constexpr uint32_t VSTG  = 64 * PV * 2;           // 9216 (x3 = 27648 <= 36864)

    extern __shared__ char smem[];
    const uint32_t sb = smem_u32(smem);
    const int t = threadIdx.x, lane = t & 31, w = t >> 5;
    const int bh = blockIdx.y, m0 = blockIdx.x * 32;
    const __half* qg = q  + (((long long)bh) << 16) + m0 * 64;
    const __half* kg = k  + (((long long)bh) << 16);
    const __half* vg = vT + (((long long)bh) << 16);
    const long long orow = (((long long)bh) << 20) + (long long)m0 * 1024;

    // ---- Phase 1: QK^T ----
    { int row = t >> 3, seg = t & 7;
      cp_async16(sb + Q_OFF + (uint32_t)(row * PQ + seg * 8) * 2,
                 qg + row * 64 + seg * 8); }
    CP_COMMIT();

    auto issueK = [&](int c, int buf) {
        #pragma unroll
        for (int i = 0; i < 4; i++) {
            int idx = t + i * 256;
            int row = idx >> 3, seg = idx & 7;
            cp_async16(sb + K_OFF + buf * KSTG + (uint32_t)(row * PQ + seg * 8) * 2,
                       kg + (long long)(c * 128 + row) * 64 + seg * 8);
        }
    };
    issueK(0, 0);
    CP_COMMIT();
    CP_WAIT(1);
    __syncthreads();

    uint32_t aq[2][4][4];
    #pragma unroll
    for (int mt = 0; mt < 2; mt++)
        #pragma unroll
        for (int ks = 0; ks < 4; ks++)
            ldmx4(aq[mt][ks], sb + Q_OFF + (uint32_t)((mt * 16 + (lane & 15)) * PQ
                                                      + ks * 16 + (lane >> 4) * 8) * 2);

    for (int c = 0; c < 8; c++) {
        const int buf = c & 1;
        if (c + 1 < 8) { issueK(c + 1, buf ^ 1); CP_COMMIT(); CP_WAIT(1); }
        else           { CP_WAIT(0); }
        __syncthreads();

        float acc[2][2][4] = {};
        const uint32_t kb = sb + K_OFF + buf * KSTG;
        #pragma unroll
        for (int ks = 0; ks < 4; ks++) {
            uint32_t bf[2][2];
            #pragma unroll
            for (int nt = 0; nt < 2; nt++)
                ldmx2(bf[nt], kb + (uint32_t)((w * 16 + nt * 8 + (lane & 7)) * PQ
                                              + ks * 16 + ((lane >> 3) & 1) * 8) * 2);
            #pragma unroll
            for (int mt = 0; mt < 2; mt++)
                #pragma unroll
                for (int nt = 0; nt < 2; nt++)
                    mma16(acc[mt][nt], aq[mt][ks], bf[nt]);
        }
        // epilogue: stream attn_s direct + S16 fp16 copy
        #pragma unroll
        for (int mt = 0; mt < 2; mt++)
            #pragma unroll
            for (int nt = 0; nt < 2; nt++) {
                int r   = mt * 16 + (lane >> 2);
                int col = c * 128 + w * 16 + nt * 8 + (lane & 3) * 2;
                float2 v0 = make_float2(acc[mt][nt][0] * SCALE_, acc[mt][nt][1] * SCALE_);
                float2 v1 = make_float2(acc[mt][nt][2] * SCALE_, acc[mt][nt][3] * SCALE_);
                *(float2*)&attn_s[orow + (long long)r * 1024 + col]       = v0;
                *(float2*)&attn_s[orow + (long long)(r + 8) * 1024 + col] = v1;
                *(__half2*)(smem + (uint32_t)(r * P16 + col) * 2)
                    = __floats2half2_rn(v0.x, v0.y);
                *(__half2*)(smem + (uint32_t)((r + 8) * P16 + col) * 2)
                    = __floats2half2_rn(v1.x, v1.y);
            }
        __syncthreads();
    }

    // prefetch V slots 0,1 (overlaps softmax)
    auto issueV = [&](int kt, int slot) {
        #pragma unroll
        for (int i = 0; i < 2; i++) {            // 64 rows x 8 segs / 256 thr
            int idx = t + i * 256;
            int row = idx >> 3, seg = idx & 7;
            cp_async16(sb + K_OFF + slot * VSTG + (uint32_t)(row * PV + seg * 8) * 2,
                       vg + (long long)row * 1024 + kt * 64 + seg * 8);
        }
    };
    issueV(0, 0); CP_COMMIT();
    issueV(1, 1); CP_COMMIT();

    // ---- Phase 2: softmax (warp w owns rows w*4..w*4+3, row-exclusive) ----
    for (int rr = 0; rr < 4; rr++) {
        const int r = w * 4 + rr;
        float4 vv[8];
        float m = -1e30f;
        #pragma unroll
        for (int i = 0; i < 8; i++) {
            uint2 u = *(uint2*)(smem + (uint32_t)(r * P16 + lane * 4 + i * 128) * 2);
            float2 f0 = __half22float2(*(__half2*)&u.x);
            float2 f1 = __half22float2(*(__half2*)&u.y);
            vv[i] = make_float4(f0.x, f0.y, f1.x, f1.y);
            m = fmaxf(m, fmaxf(fmaxf(vv[i].x, vv[i].y), fmaxf(vv[i].z, vv[i].w)));
        }
        #pragma unroll
        for (int o = 16; o; o >>= 1) m = fmaxf(m, __shfl_xor_sync(0xffffffffu, m, o));
        float sum = 0.0f;
        #pragma unroll
        for (int i = 0; i < 8; i++) {
            vv[i].x = __expf(vv[i].x - m); vv[i].y = __expf(vv[i].y - m);
            vv[i].z = __expf(vv[i].z - m); vv[i].w = __expf(vv[i].w - m);
            sum += vv[i].x + vv[i].y + vv[i].z + vv[i].w;
        }
        #pragma unroll
        for (int o = 16; o; o >>= 1) sum += __shfl_xor_sync(0xffffffffu, sum, o);
        const float inv = 1.0f / sum;
        const long long rb = orow + (long long)r * 1024;
        #pragma unroll
        for (int i = 0; i < 8; i++) {
            float4 wv = make_float4(vv[i].x * inv, vv[i].y * inv,
                                    vv[i].z * inv, vv[i].w * inv);
            *(float4*)&attn_w[rb + lane * 4 + i * 128] = wv;
            uint2 u;
            *(__half2*)&u.x = __floats2half2_rn(wv.x, wv.y);
            *(__half2*)&u.y = __floats2half2_rn(wv.z, wv.w);
            *(uint2*)(smem + (uint32_t)(r * P16 + lane * 4 + i * 128) * 2) = u;
        }
    }

    // ---- Phase 3: ctx = P(S16) @ vT^T  (C 32x64), 3-stage, 1 sync/iter ----
    const int wm = (w >> 2) * 16;          // 2 warps along m
    const int wn = (w & 3) * 16;           // 4 warps along n
    float acc3[2][4] = {};

    for (int kt = 0; kt < 16; kt++) {
        if (kt + 1 < 16) { CP_WAIT(1); } else { CP_WAIT(0); }
        __syncthreads();

        const uint32_t vb = sb + K_OFF + (kt % 3) * VSTG;
        #pragma unroll
        for (int ks = 0; ks < 4; ks++) {
            uint32_t af[4], bf[2][2];
            ldmx4(af, sb + (uint32_t)((wm + (lane & 15)) * P16
                                      + kt * 64 + ks * 16 + (lane >> 4) * 8) * 2);
            #pragma unroll
            for (int nt = 0; nt < 2; nt++)
                ldmx2(bf[nt], vb + (uint32_t)((wn + nt * 8 + (lane & 7)) * PV
                                              + ks * 16 + ((lane >> 3) & 1) * 8) * 2);
            #pragma unroll
            for (int nt = 0; nt < 2; nt++)
                mma16(acc3[nt], af, bf[nt]);
        }
        if (kt + 2 < 16) { issueV(kt + 2, (kt + 2) % 3); CP_COMMIT(); }
    }
    __syncthreads();

    // ctx epilogue: fp16 stage (Q_OFF area, pitch 68 halves) -> coalesced gmem
    #pragma unroll
    for (int nt = 0; nt < 2; nt++) {
        int r  = lane >> 2;
        int cc = wn + nt * 8 + (lane & 3) * 2;
        *(__half2*)(smem + Q_OFF + (uint32_t)((wm + r) * 68 + cc) * 2)
            = __floats2half2_rn(acc3[nt][0], acc3[nt][1]);
        *(__half2*)(smem + Q_OFF + (uint32_t)((wm + r + 8) * 68 + cc) * 2)
            = __floats2half2_rn(acc3[nt][2], acc3[nt][3]);
    }
    __syncthreads();

    const int b = bh >> 4, h = bh & 15;
    #pragma unroll
    for (int i = 0; i < 2; i++) {
        int idx = t + i * 256;
        int row = idx >> 4, seg = idx & 15;
        uint2 u = *(uint2*)(smem + Q_OFF + (uint32_t)(row * 68 + seg * 4) * 2);
        *(uint2*)&ctx[((long long)(b * SEQ_ + m0 + row)) * DM_ + h * DK_ + seg * 4] = u;
    }
}

// ---------------------------------------------------------------------------
// fp32 -> fp16 elementwise: one launch converts Q, K, V (blockIdx.y selects)
// ---------------------------------------------------------------------------
__global__ __launch_bounds__(256)
void f2h_all(const float* __restrict__ x0, const float* __restrict__ x1,
             const float* __restrict__ x2,
             __half* __restrict__ y0, __half* __restrict__ y1,
             __half* __restrict__ y2, int n4)
{
    int i = blockIdx.x * 256 + threadIdx.x;
    if (i >= n4) return;
    const float* x = blockIdx.y == 0 ? x0 : blockIdx.y == 1 ? x1 : x2;
    __half*      y = blockIdx.y == 0 ? y0 : blockIdx.y == 1 ? y1 : y2;
    ((uint2*)y)[i] = f4_to_h4(((const float4*)x)[i]);
}

// ---------------------------------------------------------------------------
// 1024x1024 transpose + convert to half: one launch does all 4 weights
// ---------------------------------------------------------------------------
__global__ __launch_bounds__(256)
void transpose_all(const float* __restrict__ s0, const float* __restrict__ s1,
                   const float* __restrict__ s2, const float* __restrict__ s3,
                   __half* __restrict__ d0, __half* __restrict__ d1,
                   __half* __restrict__ d2, __half* __restrict__ d3)
{
    const float* W  = blockIdx.z == 0 ? s0 : blockIdx.z == 1 ? s1
                    : blockIdx.z == 2 ? s2 : s3;
    __half*      WT = blockIdx.z == 0 ? d0 : blockIdx.z == 1 ? d1
                    : blockIdx.z == 2 ? d2 : d3;
    __shared__ float tile[32][33];
    int bx = blockIdx.x * 32, by = blockIdx.y * 32;
    int tx = threadIdx.x & 31, ty = threadIdx.x >> 5;
    #pragma unroll
    for (int j = ty; j < 32; j += 8)
        tile[j][tx] = W[(long long)(by + j) * DM_ + bx + tx];
    __syncthreads();
    #pragma unroll
    for (int j = ty; j < 32; j += 8)
        WT[(long long)(bx + j) * DM_ + by + tx] = __float2half(tile[tx][j]);
}

// ---------------------------------------------------------------------------
// Launch
// ---------------------------------------------------------------------------
static constexpr int SMEM_BIG   = 128 * (128 + 4) * 4;            // 67584 >= 3*20480
static constexpr int SMEM_FUSED = 32 * 1032 * 2 + 4608 + 2 * 128 * 72 * 2; // 107520

extern "C" void kernel_launch(void* const* d_in, const int* in_sizes, int n_in,
                              void* d_out, int out_size)
{
    const float* Q    = (const float*)d_in[0];
    const float* K    = (const float*)d_in[1];
    const float* V    = (const float*)d_in[2];
    const float* WQ_w = (const float*)d_in[3];
    const float* WQ_b = (const float*)d_in[4];
    const float* WK_w = (const float*)d_in[5];
    const float* WK_b = (const float*)d_in[6];
    const float* WV_w = (const float*)d_in[7];
    const float* WV_b = (const float*)d_in[8];
    const float* Wo_w = (const float*)d_in[9];
    const float* Wo_b = (const float*)d_in[10];

    float* out    = (float*)d_out;
    float* attn_w = out    + (long long)TOK_ * DM_;
    float* attn_s = attn_w + (long long)NBH_ * SEQ_ * SEQ_;

    __half *p_Q16, *p_K16, *p_V16, *p_q, *p_k, *p_vT, *p_ctx;
    __half *p_wqT, *p_wkT, *p_wvT, *p_woT;
    cudaGetSymbolAddress((void**)&p_Q16, g_Q16);
    cudaGetSymbolAddress((void**)&p_K16, g_K16);
    cudaGetSymbolAddress((void**)&p_V16, g_V16);
    cudaGetSymbolAddress((void**)&p_q,   g_q);
    cudaGetSymbolAddress((void**)&p_k,   g_k);
    cudaGetSymbolAddress((void**)&p_vT,  g_vT);
    cudaGetSymbolAddress((void**)&p_ctx, g_ctx);
    cudaGetSymbolAddress((void**)&p_wqT, g_wqT);
    cudaGetSymbolAddress((void**)&p_wkT, g_wkT);
    cudaGetSymbolAddress((void**)&p_wvT, g_wvT);
    cudaGetSymbolAddress((void**)&p_woT, g_woT);

    cudaFuncSetAttribute(gemm_h<__half,128,64,32,1>, cudaFuncAttributeMaxDynamicSharedMemorySize, SMEM_BIG);
    cudaFuncSetAttribute(gemm_h<__half,128,64,32,2>, cudaFuncAttributeMaxDynamicSharedMemorySize, SMEM_BIG);
    cudaFuncSetAttribute(gemm_h<float ,128,64,32,0>, cudaFuncAttributeMaxDynamicSharedMemorySize, SMEM_BIG);
    cudaFuncSetAttribute(fused_attn, cudaFuncAttributeMaxDynamicSharedMemorySize, SMEM_FUSED);

    const int n4 = TOK_ * DM_ / 4;

    f2h_all<<<dim3(n4 / 256, 3), 256>>>(Q, K, V, p_Q16, p_K16, p_V16, n4);
    transpose_all<<<dim3(32, 32, 4), 256>>>(WQ_w, WK_w, WV_w, Wo_w,
                                            p_wqT, p_wkT, p_wvT, p_woT);

    gemm_h<__half,128,64,32,1><<<dim3(8,64,1), 256, SMEM_BIG>>>(
        p_Q16, p_wqT, WQ_b, p_q,  TOK_, DM_, DM_);
    gemm_h<__half,128,64,32,1><<<dim3(8,64,1), 256, SMEM_BIG>>>(
        p_K16, p_wkT, WK_b, p_k,  TOK_, DM_, DM_);
    gemm_h<__half,128,64,32,2><<<dim3(8,64,1), 256, SMEM_BIG>>>(
        p_V16, p_wvT, WV_b, p_vT, TOK_, DM_, DM_);

    // fully fused attention (scores + softmax + ctx)
    fused_attn<<<dim3(32,128), 256, SMEM_FUSED>>>(
        p_q, p_k, p_vT, attn_s, attn_w, p_ctx);

    // output projection (fp32 out + bias)
    gemm_h<float,128,64,32,0><<<dim3(8,64,1), 256, SMEM_BIG>>>(
        p_ctx, p_woT, Wo_b, out, TOK_, DM_, DM_);
}